// round 8
// baseline (speedup 1.0000x reference)
#include <cuda_runtime.h>
#include <cuda_bf16.h>
#include <cuda_fp16.h>
#include <cstdint>

// Problem: MaskedSelfAttention  B=2, S=2048, E=1024, H=16, D=64, causal.
// R7: fp16 intermediates end-to-end (Q/K/V/A stored as half; precision-identical
//     to converting in-consumer). GEMM + attn mainloops unchanged from R6.

#define TS   2048
#define EMB  1024
#define NHEADS 16
#define HD   64
#define ROWS (2*TS)

__device__ __half g_Qh[ROWS*EMB];
__device__ __half g_Kh[ROWS*EMB];
__device__ __half g_Vh[ROWS*EMB];
__device__ __half g_Ah[ROWS*EMB];

__device__ __forceinline__ void mma_f16(float* d, const uint32_t* a, const uint32_t* b) {
    asm volatile(
        "mma.sync.aligned.m16n8k16.row.col.f32.f16.f16.f32 "
        "{%0,%1,%2,%3}, {%4,%5,%6,%7}, {%8,%9}, {%0,%1,%2,%3};"
        : "+f"(d[0]), "+f"(d[1]), "+f"(d[2]), "+f"(d[3])
        : "r"(a[0]), "r"(a[1]), "r"(a[2]), "r"(a[3]), "r"(b[0]), "r"(b[1]));
}

__device__ __forceinline__ uint32_t pack_h2(float x, float y) {
    __half2 h = __floats2half2_rn(x, y);
    return *(uint32_t*)&h;
}

__device__ __forceinline__ uint32_t prm(uint32_t a, uint32_t b, uint32_t sel) {
    uint32_t r;
    asm("prmt.b32 %0, %1, %2, %3;" : "=r"(r) : "r"(a), "r"(b), "r"(sel));
    return r;
}

// exp2 on the FMA/ALU pipes (no MUFU).
__device__ __forceinline__ float exp2p(float d) {
    d = fmaxf(d, -120.f);
    float t = d + 12582912.f;
    float f = d - (t - 12582912.f);
    uint32_t e = (__float_as_uint(t) + (127u - 0x4B400000u)) << 23;
    float p = 1.3333558146e-3f;
    p = fmaf(p, f, 9.6181291076e-3f);
    p = fmaf(p, f, 5.5504108665e-2f);
    p = fmaf(p, f, 2.4022650696e-1f);
    p = fmaf(p, f, 6.9314718056e-1f);
    p = fmaf(p, f, 1.0f);
    return p * __uint_as_float(e);
}

__device__ __forceinline__ float qmax(float v) {
    v = fmaxf(v, __shfl_xor_sync(0xffffffffu, v, 1));
    v = fmaxf(v, __shfl_xor_sync(0xffffffffu, v, 2));
    return v;
}
__device__ __forceinline__ float qsum(float v) {
    v += __shfl_xor_sync(0xffffffffu, v, 1);
    v += __shfl_xor_sync(0xffffffffu, v, 2);
    return v;
}

// ---------------------------------------------------------------------------
// fp16 GEMM core: C[128x128 tile] = A[M,1024] * B[1024,1024]^T (+bias).
// A may be fp32 or fp16 in gmem; B fp32; C fp32 or fp16.  (R6 mainloop.)
// ---------------------------------------------------------------------------
#define KW 20
#define TILE_W (128 * KW)
#define BUF_W  (2 * TILE_W)

template <bool AHALF, bool OUTHALF>
__device__ __forceinline__ void gemm_f16_body(
    const void* __restrict__ Aptr, const float* __restrict__ B,
    const float* __restrict__ bias, void* __restrict__ Cptr,
    int bm, int bn, uint32_t* sm)
{
    const float*  Af = (const float*)Aptr;
    const __half* Ah = (const __half*)Aptr;
    const int tid  = threadIdx.x;
    const int lane = tid & 31, warp = tid >> 5;
    const int g    = lane >> 2, tig = lane & 3;
    const int wm   = warp >> 1, wn = warp & 1;

    int lrow[4], lc4[4];
#pragma unroll
    for (int it = 0; it < 4; it++) {
        int v = tid + it * 256;
        lrow[it] = v >> 3;
        lc4[it]  = (v & 7) * 4;
    }

    float acc[2][8][4];
#pragma unroll
    for (int mi = 0; mi < 2; mi++)
#pragma unroll
        for (int ni = 0; ni < 8; ni++)
#pragma unroll
            for (int j = 0; j < 4; j++) acc[mi][ni][j] = 0.f;

    // Prologue: tile 0 -> stage 0
#pragma unroll
    for (int it = 0; it < 4; it++) {
        uint2 ua;
        if (AHALF) {
            ua = *(const uint2*)&Ah[(size_t)(bm + lrow[it]) * EMB + lc4[it]];
        } else {
            float4 a = *(const float4*)&Af[(size_t)(bm + lrow[it]) * EMB + lc4[it]];
            ua = make_uint2(pack_h2(a.x, a.y), pack_h2(a.z, a.w));
        }
        float4 b = *(const float4*)&B[(size_t)(bn + lrow[it]) * EMB + lc4[it]];
        *(uint2*)&sm[lrow[it] * KW + lc4[it] / 2] = ua;
        *(uint2*)&sm[TILE_W + lrow[it] * KW + lc4[it] / 2] =
            make_uint2(pack_h2(b.x, b.y), pack_h2(b.z, b.w));
    }
    __syncthreads();

    for (int ks = 0; ks < 32; ks++) {
        const int cur = ks & 1;
        const uint32_t* as = sm + cur * BUF_W + (wm * 32) * KW;
        const uint32_t* bs = sm + cur * BUF_W + TILE_W + (wn * 64) * KW;

        uint2  rah[4];
        float4 raf[4], rb[4];
        if (ks + 1 < 32) {
#pragma unroll
            for (int it = 0; it < 4; it++) {
                if (AHALF)
                    rah[it] = *(const uint2*)&Ah[(size_t)(bm + lrow[it]) * EMB + (ks + 1) * 32 + lc4[it]];
                else
                    raf[it] = *(const float4*)&Af[(size_t)(bm + lrow[it]) * EMB + (ks + 1) * 32 + lc4[it]];
                rb[it] = *(const float4*)&B[(size_t)(bn + lrow[it]) * EMB + (ks + 1) * 32 + lc4[it]];
            }
        }

#pragma unroll
        for (int kk = 0; kk < 2; kk++) {
            const int k0 = kk * 8;
            uint32_t af[2][4];
#pragma unroll
            for (int mi = 0; mi < 2; mi++) {
                int r = mi * 16 + g;
                af[mi][0] = as[(r    ) * KW + k0 + tig];
                af[mi][1] = as[(r + 8) * KW + k0 + tig];
                af[mi][2] = as[(r    ) * KW + k0 + 4 + tig];
                af[mi][3] = as[(r + 8) * KW + k0 + 4 + tig];
            }
#pragma unroll
            for (int ni = 0; ni < 8; ni++) {
                uint32_t bf[2];
                int nr = ni * 8 + g;
                bf[0] = bs[nr * KW + k0 + tig];
                bf[1] = bs[nr * KW + k0 + 4 + tig];
                mma_f16(acc[0][ni], af[0], bf);
                mma_f16(acc[1][ni], af[1], bf);
            }
        }

        if (ks + 1 < 32) {
            const int nxt = cur ^ 1;
            uint32_t* an  = sm + nxt * BUF_W;
            uint32_t* bnp = an + TILE_W;
#pragma unroll
            for (int it = 0; it < 4; it++) {
                uint2 ua;
                if (AHALF) ua = rah[it];
                else ua = make_uint2(pack_h2(raf[it].x, raf[it].y), pack_h2(raf[it].z, raf[it].w));
                *(uint2*)&an[lrow[it] * KW + lc4[it] / 2] = ua;
                *(uint2*)&bnp[lrow[it] * KW + lc4[it] / 2] =
                    make_uint2(pack_h2(rb[it].x, rb[it].y), pack_h2(rb[it].z, rb[it].w));
            }
            __syncthreads();
        }
    }

#pragma unroll
    for (int mi = 0; mi < 2; mi++) {
        int r0 = bm + wm * 32 + mi * 16 + g;
#pragma unroll
        for (int ni = 0; ni < 8; ni++) {
            int col = bn + wn * 64 + ni * 8 + 2 * tig;
            float b0 = 0.f, b1 = 0.f;
            if (bias) { b0 = bias[col]; b1 = bias[col + 1]; }
            float c0 = acc[mi][ni][0] + b0, c1 = acc[mi][ni][1] + b1;
            float c2 = acc[mi][ni][2] + b0, c3 = acc[mi][ni][3] + b1;
            if (OUTHALF) {
                __half* Ch = (__half*)Cptr;
                *(uint32_t*)&Ch[(size_t)r0 * EMB + col]       = pack_h2(c0, c1);
                *(uint32_t*)&Ch[(size_t)(r0 + 8) * EMB + col] = pack_h2(c2, c3);
            } else {
                float* Cf = (float*)Cptr;
                *(float2*)&Cf[(size_t)r0 * EMB + col]       = make_float2(c0, c1);
                *(float2*)&Cf[(size_t)(r0 + 8) * EMB + col] = make_float2(c2, c3);
            }
        }
    }
}

// Fused QKV: grid (24, 32); blockIdx.x>>3 selects {Wq,Wk,Wv} -> {Q,K,V} (half out).
__global__ __launch_bounds__(256) void gemm_qkv(
    const float* __restrict__ X,
    const float* __restrict__ Wq, const float* __restrict__ Wk,
    const float* __restrict__ Wv,
    __half* __restrict__ Qo, __half* __restrict__ Ko, __half* __restrict__ Vo)
{
    __shared__ uint32_t sm[2 * BUF_W];
    const int wb = blockIdx.x >> 3;
    const int bn = (blockIdx.x & 7) * 128;
    const int bm = blockIdx.y * 128;
    const float* B = (wb == 0) ? Wq : (wb == 1) ? Wk : Wv;
    __half*      C = (wb == 0) ? Qo : (wb == 1) ? Ko : Vo;
    gemm_f16_body<false, true>(X, B, nullptr, C, bm, bn, sm);
}

// Output projection: A is half (attn out), C fp32 (+bias).
__global__ __launch_bounds__(256) void gemm_out(
    const __half* __restrict__ A, const float* __restrict__ W,
    const float* __restrict__ bias, float* __restrict__ C)
{
    __shared__ uint32_t sm[2 * BUF_W];
    gemm_f16_body<true, false>(A, W, bias, C, blockIdx.y * 128, blockIdx.x * 128, sm);
}

// ---------------------------------------------------------------------------
// Flash attention (causal), fp16 mma + polynomial exp2 softmax.
// All I/O fp16. Smem stride 80 halves = 40 words (conflict-free: 8g+tig).
// ---------------------------------------------------------------------------
#define AW 40    // word stride (80 halves)

__global__ __launch_bounds__(256, 2) void attn_mma(
    const __half* __restrict__ Q, const __half* __restrict__ K,
    const __half* __restrict__ V, __half* __restrict__ O)
{
    __shared__ uint32_t KsW[64 * AW];
    __shared__ uint32_t VtW[64 * AW];
    __shared__ uint32_t PsW[128 * AW];

    const int tid  = threadIdx.x;
    const int lane = tid & 31, w = tid >> 5;
    const int g    = lane >> 2, tig = lane & 3;
    const int qt   = 15 - blockIdx.x;
    const int bh   = blockIdx.y;
    const int b    = bh >> 4, h = bh & 15;
    const size_t base  = (size_t)b * TS * EMB + (size_t)h * HD;
    const int    qbase = qt * 128;

    // ---- Stage Q tile into Ps (pure copy), lift to fragments.
#pragma unroll
    for (int it = 0; it < 4; it++) {
        int v = tid + it * 256;
        int row = v >> 3, c = v & 7;          // c: 8-half group
        uint2 t = *(const uint2*)&Q[base + (size_t)(qbase + row) * EMB + c * 8];
        uint2 t2 = *(const uint2*)&Q[base + (size_t)(qbase + row) * EMB + c * 8 + 4];
        *(uint4*)&PsW[row * AW + c * 4] = make_uint4(t.x, t.y, t2.x, t2.y);
    }
    __syncthreads();

    uint32_t qa[4][4];
    {
        const int r0 = w * 16 + g;
#pragma unroll
        for (int kc = 0; kc < 4; kc++) {
            qa[kc][0] = PsW[(r0    ) * AW + kc * 8 + tig];
            qa[kc][1] = PsW[(r0 + 8) * AW + kc * 8 + tig];
            qa[kc][2] = PsW[(r0    ) * AW + kc * 8 + 4 + tig];
            qa[kc][3] = PsW[(r0 + 8) * AW + kc * 8 + 4 + tig];
        }
    }
    __syncthreads();

    float m0 = -1e30f, m1 = -1e30f, l0 = 0.f, l1 = 0.f;
    float o[8][4];
#pragma unroll
    for (int ni = 0; ni < 8; ni++)
#pragma unroll
        for (int j = 0; j < 4; j++) o[ni][j] = 0.f;

    const float scale2 = 0.125f * 1.44269504089f;
    const int nkt = 2 * qt + 2;
    const int qrow_max = qbase + w * 16 + 15;

    for (int kt = 0; kt < nkt; kt++) {
        __syncthreads();
        // K tile [key][d]: straight uint4 copy.
#pragma unroll
        for (int it = 0; it < 2; it++) {
            int v = tid + it * 256;
            int row = v >> 3, c = v & 7;
            uint2 t  = *(const uint2*)&K[base + (size_t)(kt * 64 + row) * EMB + c * 8];
            uint2 t2 = *(const uint2*)&K[base + (size_t)(kt * 64 + row) * EMB + c * 8 + 4];
            *(uint4*)&KsW[row * AW + c * 4] = make_uint4(t.x, t.y, t2.x, t2.y);
        }
        // V tile transposed via PRMT: Vt[d][key-pairs].
#pragma unroll
        for (int it = 0; it < 2; it++) {
            int u  = tid + it * 256;
            int kp = u & 31, c4 = (u >> 5) * 4;
            const __half* va = &V[base + (size_t)(kt * 64 + 2 * kp) * EMB + c4];
            uint2 fa = *(const uint2*)va;
            uint2 fb = *(const uint2*)(va + EMB);
            VtW[(c4 + 0) * AW + kp] = prm(fa.x, fb.x, 0x5410);
            VtW[(c4 + 1) * AW + kp] = prm(fa.x, fb.x, 0x7632);
            VtW[(c4 + 2) * AW + kp] = prm(fa.y, fb.y, 0x5410);
            VtW[(c4 + 3) * AW + kp] = prm(fa.y, fb.y, 0x7632);
        }
        __syncthreads();

        if (kt * 64 > qrow_max) continue;

        // ---- Scores
        float sc[8][4];
#pragma unroll
        for (int ni = 0; ni < 8; ni++) {
            sc[ni][0] = sc[ni][1] = sc[ni][2] = sc[ni][3] = 0.f;
            int nr = ni * 8 + g;
#pragma unroll
            for (int kc = 0; kc < 4; kc++) {
                uint32_t bf[2];
                bf[0] = KsW[nr * AW + kc * 8 + tig];
                bf[1] = KsW[nr * AW + kc * 8 + 4 + tig];
                mma_f16(sc[ni], qa[kc], bf);
            }
        }

        const bool diag = (kt * 64 + 63 > qbase + w * 16);
        const int qg0 = qbase + w * 16 + g, qg1 = qg0 + 8;
#pragma unroll
        for (int ni = 0; ni < 8; ni++) {
#pragma unroll
            for (int j = 0; j < 4; j++) sc[ni][j] *= scale2;
            if (diag) {
                int kg = kt * 64 + ni * 8 + 2 * tig;
                if (kg     > qg0) sc[ni][0] = -1e30f;
                if (kg + 1 > qg0) sc[ni][1] = -1e30f;
                if (kg     > qg1) sc[ni][2] = -1e30f;
                if (kg + 1 > qg1) sc[ni][3] = -1e30f;
            }
        }

        // ---- Online softmax (base-2), P -> Ps
        float rm0 = -1e30f, rm1 = -1e30f;
#pragma unroll
        for (int ni = 0; ni < 8; ni++) {
            rm0 = fmaxf(rm0, fmaxf(sc[ni][0], sc[ni][1]));
            rm1 = fmaxf(rm1, fmaxf(sc[ni][2], sc[ni][3]));
        }
        rm0 = qmax(rm0); rm1 = qmax(rm1);
        float mn0 = fmaxf(m0, rm0), mn1 = fmaxf(m1, rm1);
        float a0 = exp2p(m0 - mn0), a1 = exp2p(m1 - mn1);
        m0 = mn0; m1 = mn1;
#pragma unroll
        for (int ni = 0; ni < 8; ni++) {
            o[ni][0] *= a0; o[ni][1] *= a0;
            o[ni][2] *= a1; o[ni][3] *= a1;
        }
        float s0 = 0.f, s1 = 0.f;
        const int pr0 = w * 16 + g;
#pragma unroll
        for (int ni = 0; ni < 8; ni++) {
            float p0 = exp2p(sc[ni][0] - mn0);
            float p1 = exp2p(sc[ni][1] - mn0);
            float p2 = exp2p(sc[ni][2] - mn1);
            float p3 = exp2p(sc[ni][3] - mn1);
            s0 += p0 + p1; s1 += p2 + p3;
            PsW[(pr0    ) * AW + ni * 4 + tig] = pack_h2(p0, p1);
            PsW[(pr0 + 8) * AW + ni * 4 + tig] = pack_h2(p2, p3);
        }
        l0 = l0 * a0 + qsum(s0);
        l1 = l1 * a1 + qsum(s1);
        __syncwarp();

        // ---- PV
#pragma unroll
        for (int kc = 0; kc < 4; kc++) {
            uint32_t pa[4];
            pa[0] = PsW[(pr0    ) * AW + kc * 8 + tig];
            pa[1] = PsW[(pr0 + 8) * AW + kc * 8 + tig];
            pa[2] = PsW[(pr0    ) * AW + kc * 8 + 4 + tig];
            pa[3] = PsW[(pr0 + 8) * AW + kc * 8 + 4 + tig];
#pragma unroll
            for (int nd = 0; nd < 8; nd++) {
                uint32_t bf[2];
                int dr = nd * 8 + g;
                bf[0] = VtW[dr * AW + kc * 8 + tig];
                bf[1] = VtW[dr * AW + kc * 8 + 4 + tig];
                mma_f16(o[nd], pa, bf);
            }
        }
        __syncwarp();
    }

    // ---- Normalize + store (half)
    const float inv0 = 1.f / l0, inv1 = 1.f / l1;
    const int q0 = qbase + w * 16 + g;
#pragma unroll
    for (int nd = 0; nd < 8; nd++) {
        int col = nd * 8 + 2 * tig;
        *(uint32_t*)&O[base + (size_t)q0 * EMB + col] =
            pack_h2(o[nd][0] * inv0, o[nd][1] * inv0);
        *(uint32_t*)&O[base + (size_t)(q0 + 8) * EMB + col] =
            pack_h2(o[nd][2] * inv1, o[nd][3] * inv1);
    }
}

// ---------------------------------------------------------------------------
extern "C" void kernel_launch(void* const* d_in, const int* in_sizes, int n_in,
                              void* d_out, int out_size)
{
    const float* x  = (const float*)d_in[0];
    // d_in[1] = mask (exact causal tril) -- applied analytically
    const float* Wq = (const float*)d_in[2];
    const float* Wk = (const float*)d_in[3];
    const float* Wv = (const float*)d_in[4];
    const float* Wo = (const float*)d_in[5];
    const float* bo = (const float*)d_in[6];
    float* out = (float*)d_out;

    __half *Qh, *Kh, *Vh, *Ah;
    cudaGetSymbolAddress((void**)&Qh, g_Qh);
    cudaGetSymbolAddress((void**)&Kh, g_Kh);
    cudaGetSymbolAddress((void**)&Vh, g_Vh);
    cudaGetSymbolAddress((void**)&Ah, g_Ah);

    dim3 qkvgrid(24, ROWS / 128);       // (24, 32)
    gemm_qkv<<<qkvgrid, 256>>>(x, Wq, Wk, Wv, Qh, Kh, Vh);

    dim3 agrid(16, 2 * NHEADS);         // (16, 32)
    attn_mma<<<agrid, 256>>>(Qh, Kh, Vh, Ah);

    dim3 ogrid(EMB / 128, ROWS / 128);  // (8, 32)
    gemm_out<<<ogrid, 256>>>(Ah, Wo, bo, out);
}

// round 9
// speedup vs baseline: 1.1493x; 1.1493x over previous
#include <cuda_runtime.h>
#include <cuda_bf16.h>
#include <cuda_fp16.h>
#include <cstdint>

// Problem: MaskedSelfAttention  B=2, S=2048, E=1024, H=16, D=64, causal.
// R9: R7's fp16-everywhere pipeline with the attention smem stride reverted to
//     36 words (4g+tig -> conflict-free). R7's 40-word stride caused 2-way
//     LDS conflicts (8g+tig covers only 16 banks) => the 355->396 regression.

#define TS   2048
#define EMB  1024
#define NHEADS 16
#define HD   64
#define ROWS (2*TS)

__device__ __half g_Qh[ROWS*EMB];
__device__ __half g_Kh[ROWS*EMB];
__device__ __half g_Vh[ROWS*EMB];
__device__ __half g_Ah[ROWS*EMB];

__device__ __forceinline__ void mma_f16(float* d, const uint32_t* a, const uint32_t* b) {
    asm volatile(
        "mma.sync.aligned.m16n8k16.row.col.f32.f16.f16.f32 "
        "{%0,%1,%2,%3}, {%4,%5,%6,%7}, {%8,%9}, {%0,%1,%2,%3};"
        : "+f"(d[0]), "+f"(d[1]), "+f"(d[2]), "+f"(d[3])
        : "r"(a[0]), "r"(a[1]), "r"(a[2]), "r"(a[3]), "r"(b[0]), "r"(b[1]));
}

__device__ __forceinline__ uint32_t pack_h2(float x, float y) {
    __half2 h = __floats2half2_rn(x, y);
    return *(uint32_t*)&h;
}

__device__ __forceinline__ uint32_t prm(uint32_t a, uint32_t b, uint32_t sel) {
    uint32_t r;
    asm("prmt.b32 %0, %1, %2, %3;" : "=r"(r) : "r"(a), "r"(b), "r"(sel));
    return r;
}

// exp2 on the FMA/ALU pipes (no MUFU).
__device__ __forceinline__ float exp2p(float d) {
    d = fmaxf(d, -120.f);
    float t = d + 12582912.f;
    float f = d - (t - 12582912.f);
    uint32_t e = (__float_as_uint(t) + (127u - 0x4B400000u)) << 23;
    float p = 1.3333558146e-3f;
    p = fmaf(p, f, 9.6181291076e-3f);
    p = fmaf(p, f, 5.5504108665e-2f);
    p = fmaf(p, f, 2.4022650696e-1f);
    p = fmaf(p, f, 6.9314718056e-1f);
    p = fmaf(p, f, 1.0f);
    return p * __uint_as_float(e);
}

__device__ __forceinline__ float qmax(float v) {
    v = fmaxf(v, __shfl_xor_sync(0xffffffffu, v, 1));
    v = fmaxf(v, __shfl_xor_sync(0xffffffffu, v, 2));
    return v;
}
__device__ __forceinline__ float qsum(float v) {
    v += __shfl_xor_sync(0xffffffffu, v, 1);
    v += __shfl_xor_sync(0xffffffffu, v, 2);
    return v;
}

// ---------------------------------------------------------------------------
// fp16 GEMM core: C[128x128 tile] = A[M,1024] * B[1024,1024]^T (+bias).
// ---------------------------------------------------------------------------
#define KW 20
#define TILE_W (128 * KW)
#define BUF_W  (2 * TILE_W)

template <bool AHALF, bool OUTHALF>
__device__ __forceinline__ void gemm_f16_body(
    const void* __restrict__ Aptr, const float* __restrict__ B,
    const float* __restrict__ bias, void* __restrict__ Cptr,
    int bm, int bn, uint32_t* sm)
{
    const float*  Af = (const float*)Aptr;
    const __half* Ah = (const __half*)Aptr;
    const int tid  = threadIdx.x;
    const int lane = tid & 31, warp = tid >> 5;
    const int g    = lane >> 2, tig = lane & 3;
    const int wm   = warp >> 1, wn = warp & 1;

    int lrow[4], lc4[4];
#pragma unroll
    for (int it = 0; it < 4; it++) {
        int v = tid + it * 256;
        lrow[it] = v >> 3;
        lc4[it]  = (v & 7) * 4;
    }

    float acc[2][8][4];
#pragma unroll
    for (int mi = 0; mi < 2; mi++)
#pragma unroll
        for (int ni = 0; ni < 8; ni++)
#pragma unroll
            for (int j = 0; j < 4; j++) acc[mi][ni][j] = 0.f;

#pragma unroll
    for (int it = 0; it < 4; it++) {
        uint2 ua;
        if (AHALF) {
            ua = *(const uint2*)&Ah[(size_t)(bm + lrow[it]) * EMB + lc4[it]];
        } else {
            float4 a = *(const float4*)&Af[(size_t)(bm + lrow[it]) * EMB + lc4[it]];
            ua = make_uint2(pack_h2(a.x, a.y), pack_h2(a.z, a.w));
        }
        float4 b = *(const float4*)&B[(size_t)(bn + lrow[it]) * EMB + lc4[it]];
        *(uint2*)&sm[lrow[it] * KW + lc4[it] / 2] = ua;
        *(uint2*)&sm[TILE_W + lrow[it] * KW + lc4[it] / 2] =
            make_uint2(pack_h2(b.x, b.y), pack_h2(b.z, b.w));
    }
    __syncthreads();

    for (int ks = 0; ks < 32; ks++) {
        const int cur = ks & 1;
        const uint32_t* as = sm + cur * BUF_W + (wm * 32) * KW;
        const uint32_t* bs = sm + cur * BUF_W + TILE_W + (wn * 64) * KW;

        uint2  rah[4];
        float4 raf[4], rb[4];
        if (ks + 1 < 32) {
#pragma unroll
            for (int it = 0; it < 4; it++) {
                if (AHALF)
                    rah[it] = *(const uint2*)&Ah[(size_t)(bm + lrow[it]) * EMB + (ks + 1) * 32 + lc4[it]];
                else
                    raf[it] = *(const float4*)&Af[(size_t)(bm + lrow[it]) * EMB + (ks + 1) * 32 + lc4[it]];
                rb[it] = *(const float4*)&B[(size_t)(bn + lrow[it]) * EMB + (ks + 1) * 32 + lc4[it]];
            }
        }

#pragma unroll
        for (int kk = 0; kk < 2; kk++) {
            const int k0 = kk * 8;
            uint32_t af[2][4];
#pragma unroll
            for (int mi = 0; mi < 2; mi++) {
                int r = mi * 16 + g;
                af[mi][0] = as[(r    ) * KW + k0 + tig];
                af[mi][1] = as[(r + 8) * KW + k0 + tig];
                af[mi][2] = as[(r    ) * KW + k0 + 4 + tig];
                af[mi][3] = as[(r + 8) * KW + k0 + 4 + tig];
            }
#pragma unroll
            for (int ni = 0; ni < 8; ni++) {
                uint32_t bf[2];
                int nr = ni * 8 + g;
                bf[0] = bs[nr * KW + k0 + tig];
                bf[1] = bs[nr * KW + k0 + 4 + tig];
                mma_f16(acc[0][ni], af[0], bf);
                mma_f16(acc[1][ni], af[1], bf);
            }
        }

        if (ks + 1 < 32) {
            const int nxt = cur ^ 1;
            uint32_t* an  = sm + nxt * BUF_W;
            uint32_t* bnp = an + TILE_W;
#pragma unroll
            for (int it = 0; it < 4; it++) {
                uint2 ua;
                if (AHALF) ua = rah[it];
                else ua = make_uint2(pack_h2(raf[it].x, raf[it].y), pack_h2(raf[it].z, raf[it].w));
                *(uint2*)&an[lrow[it] * KW + lc4[it] / 2] = ua;
                *(uint2*)&bnp[lrow[it] * KW + lc4[it] / 2] =
                    make_uint2(pack_h2(rb[it].x, rb[it].y), pack_h2(rb[it].z, rb[it].w));
            }
            __syncthreads();
        }
    }

#pragma unroll
    for (int mi = 0; mi < 2; mi++) {
        int r0 = bm + wm * 32 + mi * 16 + g;
#pragma unroll
        for (int ni = 0; ni < 8; ni++) {
            int col = bn + wn * 64 + ni * 8 + 2 * tig;
            float b0 = 0.f, b1 = 0.f;
            if (bias) { b0 = bias[col]; b1 = bias[col + 1]; }
            float c0 = acc[mi][ni][0] + b0, c1 = acc[mi][ni][1] + b1;
            float c2 = acc[mi][ni][2] + b0, c3 = acc[mi][ni][3] + b1;
            if (OUTHALF) {
                __half* Ch = (__half*)Cptr;
                *(uint32_t*)&Ch[(size_t)r0 * EMB + col]       = pack_h2(c0, c1);
                *(uint32_t*)&Ch[(size_t)(r0 + 8) * EMB + col] = pack_h2(c2, c3);
            } else {
                float* Cf = (float*)Cptr;
                *(float2*)&Cf[(size_t)r0 * EMB + col]       = make_float2(c0, c1);
                *(float2*)&Cf[(size_t)(r0 + 8) * EMB + col] = make_float2(c2, c3);
            }
        }
    }
}

__global__ __launch_bounds__(256) void gemm_qkv(
    const float* __restrict__ X,
    const float* __restrict__ Wq, const float* __restrict__ Wk,
    const float* __restrict__ Wv,
    __half* __restrict__ Qo, __half* __restrict__ Ko, __half* __restrict__ Vo)
{
    __shared__ uint32_t sm[2 * BUF_W];
    const int wb = blockIdx.x >> 3;
    const int bn = (blockIdx.x & 7) * 128;
    const int bm = blockIdx.y * 128;
    const float* B = (wb == 0) ? Wq : (wb == 1) ? Wk : Wv;
    __half*      C = (wb == 0) ? Qo : (wb == 1) ? Ko : Vo;
    gemm_f16_body<false, true>(X, B, nullptr, C, bm, bn, sm);
}

__global__ __launch_bounds__(256) void gemm_out(
    const __half* __restrict__ A, const float* __restrict__ W,
    const float* __restrict__ bias, float* __restrict__ C)
{
    __shared__ uint32_t sm[2 * BUF_W];
    gemm_f16_body<true, false>(A, W, bias, C, blockIdx.y * 128, blockIdx.x * 128, sm);
}

// ---------------------------------------------------------------------------
// Flash attention (causal), fp16 mma + polynomial exp2 softmax. All I/O fp16.
// Smem stride AW=36 words (72 halves): frag address 4g+tig -> all 32 banks.
// uint4 staging OK: row*36 + c*4 is a multiple of 4 words (16B aligned).
// ---------------------------------------------------------------------------
#define AW 36

__global__ __launch_bounds__(256, 2) void attn_mma(
    const __half* __restrict__ Q, const __half* __restrict__ K,
    const __half* __restrict__ V, __half* __restrict__ O)
{
    __shared__ __align__(16) uint32_t KsW[64 * AW];
    __shared__ __align__(16) uint32_t VtW[64 * AW];
    __shared__ __align__(16) uint32_t PsW[128 * AW];

    const int tid  = threadIdx.x;
    const int lane = tid & 31, w = tid >> 5;
    const int g    = lane >> 2, tig = lane & 3;
    const int qt   = 15 - blockIdx.x;
    const int bh   = blockIdx.y;
    const int b    = bh >> 4, h = bh & 15;
    const size_t base  = (size_t)b * TS * EMB + (size_t)h * HD;
    const int    qbase = qt * 128;

    // ---- Stage Q tile into Ps (pure uint4 copy), lift to fragments.
#pragma unroll
    for (int it = 0; it < 4; it++) {
        int v = tid + it * 256;
        int row = v >> 3, c = v & 7;
        uint4 t = *(const uint4*)&Q[base + (size_t)(qbase + row) * EMB + c * 8];
        *(uint4*)&PsW[row * AW + c * 4] = t;
    }
    __syncthreads();

    uint32_t qa[4][4];
    {
        const int r0 = w * 16 + g;
#pragma unroll
        for (int kc = 0; kc < 4; kc++) {
            qa[kc][0] = PsW[(r0    ) * AW + kc * 8 + tig];
            qa[kc][1] = PsW[(r0 + 8) * AW + kc * 8 + tig];
            qa[kc][2] = PsW[(r0    ) * AW + kc * 8 + 4 + tig];
            qa[kc][3] = PsW[(r0 + 8) * AW + kc * 8 + 4 + tig];
        }
    }
    __syncthreads();

    float m0 = -1e30f, m1 = -1e30f, l0 = 0.f, l1 = 0.f;
    float o[8][4];
#pragma unroll
    for (int ni = 0; ni < 8; ni++)
#pragma unroll
        for (int j = 0; j < 4; j++) o[ni][j] = 0.f;

    const float scale2 = 0.125f * 1.44269504089f;
    const int nkt = 2 * qt + 2;
    const int qrow_max = qbase + w * 16 + 15;

    for (int kt = 0; kt < nkt; kt++) {
        __syncthreads();
        // K tile [key][d]: straight uint4 copy.
#pragma unroll
        for (int it = 0; it < 2; it++) {
            int v = tid + it * 256;
            int row = v >> 3, c = v & 7;
            uint4 t = *(const uint4*)&K[base + (size_t)(kt * 64 + row) * EMB + c * 8];
            *(uint4*)&KsW[row * AW + c * 4] = t;
        }
        // V tile transposed via PRMT: Vt[d][key-pairs].
#pragma unroll
        for (int it = 0; it < 2; it++) {
            int u  = tid + it * 256;
            int kp = u & 31, c4 = (u >> 5) * 4;
            const __half* va = &V[base + (size_t)(kt * 64 + 2 * kp) * EMB + c4];
            uint2 fa = *(const uint2*)va;
            uint2 fb = *(const uint2*)(va + EMB);
            VtW[(c4 + 0) * AW + kp] = prm(fa.x, fb.x, 0x5410);
            VtW[(c4 + 1) * AW + kp] = prm(fa.x, fb.x, 0x7632);
            VtW[(c4 + 2) * AW + kp] = prm(fa.y, fb.y, 0x5410);
            VtW[(c4 + 3) * AW + kp] = prm(fa.y, fb.y, 0x7632);
        }
        __syncthreads();

        if (kt * 64 > qrow_max) continue;

        // ---- Scores
        float sc[8][4];
#pragma unroll
        for (int ni = 0; ni < 8; ni++) {
            sc[ni][0] = sc[ni][1] = sc[ni][2] = sc[ni][3] = 0.f;
            int nr = ni * 8 + g;
#pragma unroll
            for (int kc = 0; kc < 4; kc++) {
                uint32_t bf[2];
                bf[0] = KsW[nr * AW + kc * 8 + tig];
                bf[1] = KsW[nr * AW + kc * 8 + 4 + tig];
                mma_f16(sc[ni], qa[kc], bf);
            }
        }

        const bool diag = (kt * 64 + 63 > qbase + w * 16);
        const int qg0 = qbase + w * 16 + g, qg1 = qg0 + 8;
#pragma unroll
        for (int ni = 0; ni < 8; ni++) {
#pragma unroll
            for (int j = 0; j < 4; j++) sc[ni][j] *= scale2;
            if (diag) {
                int kg = kt * 64 + ni * 8 + 2 * tig;
                if (kg     > qg0) sc[ni][0] = -1e30f;
                if (kg + 1 > qg0) sc[ni][1] = -1e30f;
                if (kg     > qg1) sc[ni][2] = -1e30f;
                if (kg + 1 > qg1) sc[ni][3] = -1e30f;
            }
        }

        // ---- Online softmax (base-2), P -> Ps
        float rm0 = -1e30f, rm1 = -1e30f;
#pragma unroll
        for (int ni = 0; ni < 8; ni++) {
            rm0 = fmaxf(rm0, fmaxf(sc[ni][0], sc[ni][1]));
            rm1 = fmaxf(rm1, fmaxf(sc[ni][2], sc[ni][3]));
        }
        rm0 = qmax(rm0); rm1 = qmax(rm1);
        float mn0 = fmaxf(m0, rm0), mn1 = fmaxf(m1, rm1);
        float a0 = exp2p(m0 - mn0), a1 = exp2p(m1 - mn1);
        m0 = mn0; m1 = mn1;
#pragma unroll
        for (int ni = 0; ni < 8; ni++) {
            o[ni][0] *= a0; o[ni][1] *= a0;
            o[ni][2] *= a1; o[ni][3] *= a1;
        }
        float s0 = 0.f, s1 = 0.f;
        const int pr0 = w * 16 + g;
#pragma unroll
        for (int ni = 0; ni < 8; ni++) {
            float p0 = exp2p(sc[ni][0] - mn0);
            float p1 = exp2p(sc[ni][1] - mn0);
            float p2 = exp2p(sc[ni][2] - mn1);
            float p3 = exp2p(sc[ni][3] - mn1);
            s0 += p0 + p1; s1 += p2 + p3;
            PsW[(pr0    ) * AW + ni * 4 + tig] = pack_h2(p0, p1);
            PsW[(pr0 + 8) * AW + ni * 4 + tig] = pack_h2(p2, p3);
        }
        l0 = l0 * a0 + qsum(s0);
        l1 = l1 * a1 + qsum(s1);
        __syncwarp();

        // ---- PV
#pragma unroll
        for (int kc = 0; kc < 4; kc++) {
            uint32_t pa[4];
            pa[0] = PsW[(pr0    ) * AW + kc * 8 + tig];
            pa[1] = PsW[(pr0 + 8) * AW + kc * 8 + tig];
            pa[2] = PsW[(pr0    ) * AW + kc * 8 + 4 + tig];
            pa[3] = PsW[(pr0 + 8) * AW + kc * 8 + 4 + tig];
#pragma unroll
            for (int nd = 0; nd < 8; nd++) {
                uint32_t bf[2];
                int dr = nd * 8 + g;
                bf[0] = VtW[dr * AW + kc * 8 + tig];
                bf[1] = VtW[dr * AW + kc * 8 + 4 + tig];
                mma_f16(o[nd], pa, bf);
            }
        }
        __syncwarp();
    }

    // ---- Normalize + store (half)
    const float inv0 = 1.f / l0, inv1 = 1.f / l1;
    const int q0 = qbase + w * 16 + g;
#pragma unroll
    for (int nd = 0; nd < 8; nd++) {
        int col = nd * 8 + 2 * tig;
        *(uint32_t*)&O[base + (size_t)q0 * EMB + col] =
            pack_h2(o[nd][0] * inv0, o[nd][1] * inv0);
        *(uint32_t*)&O[base + (size_t)(q0 + 8) * EMB + col] =
            pack_h2(o[nd][2] * inv1, o[nd][3] * inv1);
    }
}

// ---------------------------------------------------------------------------
extern "C" void kernel_launch(void* const* d_in, const int* in_sizes, int n_in,
                              void* d_out, int out_size)
{
    const float* x  = (const float*)d_in[0];
    // d_in[1] = mask (exact causal tril) -- applied analytically
    const float* Wq = (const float*)d_in[2];
    const float* Wk = (const float*)d_in[3];
    const float* Wv = (const float*)d_in[4];
    const float* Wo = (const float*)d_in[5];
    const float* bo = (const float*)d_in[6];
    float* out = (float*)d_out;

    __half *Qh, *Kh, *Vh, *Ah;
    cudaGetSymbolAddress((void**)&Qh, g_Qh);
    cudaGetSymbolAddress((void**)&Kh, g_Kh);
    cudaGetSymbolAddress((void**)&Vh, g_Vh);
    cudaGetSymbolAddress((void**)&Ah, g_Ah);

    dim3 qkvgrid(24, ROWS / 128);       // (24, 32)
    gemm_qkv<<<qkvgrid, 256>>>(x, Wq, Wk, Wv, Qh, Kh, Vh);

    dim3 agrid(16, 2 * NHEADS);         // (16, 32)
    attn_mma<<<agrid, 256>>>(Qh, Kh, Vh, Ah);

    dim3 ogrid(EMB / 128, ROWS / 128);  // (8, 32)
    gemm_out<<<ogrid, 256>>>(Ah, Wo, bo, out);
}

// round 10
// speedup vs baseline: 1.2356x; 1.0751x over previous
#include <cuda_runtime.h>
#include <cuda_bf16.h>
#include <cuda_fp16.h>
#include <cstdint>

// Problem: MaskedSelfAttention  B=2, S=2048, E=1024, H=16, D=64, causal.
// R10: prepass converts x + all weights to fp16 once (same rounding as before
//      -> precision-identical); GEMMs read pure half with BK=64 (half the
//      barriers, LDG.128 loaders, no in-loop cvt). Attention = R9 (proven).

#define TS   2048
#define EMB  1024
#define NHEADS 16
#define HD   64
#define ROWS (2*TS)

__device__ __half g_Qh[ROWS*EMB];
__device__ __half g_Kh[ROWS*EMB];
__device__ __half g_Vh[ROWS*EMB];
__device__ __half g_Ah[ROWS*EMB];
__device__ __half g_Xh[ROWS*EMB];
__device__ __half g_Wqh[EMB*EMB];
__device__ __half g_Wkh[EMB*EMB];
__device__ __half g_Wvh[EMB*EMB];
__device__ __half g_Woh[EMB*EMB];

__device__ __forceinline__ void mma_f16(float* d, const uint32_t* a, const uint32_t* b) {
    asm volatile(
        "mma.sync.aligned.m16n8k16.row.col.f32.f16.f16.f32 "
        "{%0,%1,%2,%3}, {%4,%5,%6,%7}, {%8,%9}, {%0,%1,%2,%3};"
        : "+f"(d[0]), "+f"(d[1]), "+f"(d[2]), "+f"(d[3])
        : "r"(a[0]), "r"(a[1]), "r"(a[2]), "r"(a[3]), "r"(b[0]), "r"(b[1]));
}

__device__ __forceinline__ uint32_t pack_h2(float x, float y) {
    __half2 h = __floats2half2_rn(x, y);
    return *(uint32_t*)&h;
}

__device__ __forceinline__ uint32_t prm(uint32_t a, uint32_t b, uint32_t sel) {
    uint32_t r;
    asm("prmt.b32 %0, %1, %2, %3;" : "=r"(r) : "r"(a), "r"(b), "r"(sel));
    return r;
}

// exp2 on the FMA/ALU pipes (no MUFU).
__device__ __forceinline__ float exp2p(float d) {
    d = fmaxf(d, -120.f);
    float t = d + 12582912.f;
    float f = d - (t - 12582912.f);
    uint32_t e = (__float_as_uint(t) + (127u - 0x4B400000u)) << 23;
    float p = 1.3333558146e-3f;
    p = fmaf(p, f, 9.6181291076e-3f);
    p = fmaf(p, f, 5.5504108665e-2f);
    p = fmaf(p, f, 2.4022650696e-1f);
    p = fmaf(p, f, 6.9314718056e-1f);
    p = fmaf(p, f, 1.0f);
    return p * __uint_as_float(e);
}

__device__ __forceinline__ float qmax(float v) {
    v = fmaxf(v, __shfl_xor_sync(0xffffffffu, v, 1));
    v = fmaxf(v, __shfl_xor_sync(0xffffffffu, v, 2));
    return v;
}
__device__ __forceinline__ float qsum(float v) {
    v += __shfl_xor_sync(0xffffffffu, v, 1);
    v += __shfl_xor_sync(0xffffffffu, v, 2);
    return v;
}

// ---------------------------------------------------------------------------
// Prepass: convert x (4M) + 4 weights (1M each) fp32 -> fp16. 8 elems/thread.
// ---------------------------------------------------------------------------
__global__ __launch_bounds__(256) void cvt_all(
    const float* __restrict__ X,
    const float* __restrict__ Wq, const float* __restrict__ Wk,
    const float* __restrict__ Wv, const float* __restrict__ Wo,
    __half* __restrict__ Xh, __half* __restrict__ Wqh, __half* __restrict__ Wkh,
    __half* __restrict__ Wvh, __half* __restrict__ Woh)
{
    size_t i = ((size_t)blockIdx.x * 256 + threadIdx.x) * 8;
    const float* src; __half* dst; size_t off;
    const size_t NX = (size_t)ROWS * EMB, NW = (size_t)EMB * EMB;
    if (i < NX)               { src = X;  dst = Xh;  off = i; }
    else if (i < NX + NW)     { src = Wq; dst = Wqh; off = i - NX; }
    else if (i < NX + 2*NW)   { src = Wk; dst = Wkh; off = i - NX - NW; }
    else if (i < NX + 3*NW)   { src = Wv; dst = Wvh; off = i - NX - 2*NW; }
    else                      { src = Wo; dst = Woh; off = i - NX - 3*NW; }
    float4 a = *(const float4*)&src[off];
    float4 b = *(const float4*)&src[off + 4];
    uint4 u = make_uint4(pack_h2(a.x, a.y), pack_h2(a.z, a.w),
                         pack_h2(b.x, b.y), pack_h2(b.z, b.w));
    *(uint4*)&dst[off] = u;
}

// ---------------------------------------------------------------------------
// fp16 GEMM: C[128x128 tile] = A[M,1024] * B[1024,1024]^T (+bias).
// All-half inputs. CTA 128x128, BK=64 halves, 256 threads (8 warps = 4Mx2N),
// double-buffered dynamic smem (72KB). Row stride KW=36 words: frag address
// 4g+tig -> conflict-free; loaders are pure LDG.128/STS.128.
// ---------------------------------------------------------------------------
#define KW 36
#define TILE_W (128 * KW)
#define BUF_W  (2 * TILE_W)
#define GEMM_SMEM (2 * BUF_W * 4)   // 73728 B

template <bool OUTHALF>
__device__ __forceinline__ void gemm_h_body(
    const __half* __restrict__ A, const __half* __restrict__ B,
    const float* __restrict__ bias, void* __restrict__ Cptr,
    int bm, int bn, uint32_t* sm)
{
    const int tid  = threadIdx.x;
    const int lane = tid & 31, warp = tid >> 5;
    const int g    = lane >> 2, tig = lane & 3;
    const int wm   = warp >> 1, wn = warp & 1;

    int lrow[4], lc[4];
#pragma unroll
    for (int it = 0; it < 4; it++) {
        int v = tid + it * 256;
        lrow[it] = v >> 3;
        lc[it]   = (v & 7) * 8;      // half offset within BK=64
    }

    float acc[2][8][4];
#pragma unroll
    for (int mi = 0; mi < 2; mi++)
#pragma unroll
        for (int ni = 0; ni < 8; ni++)
#pragma unroll
            for (int j = 0; j < 4; j++) acc[mi][ni][j] = 0.f;

    // Prologue: tile 0 -> stage 0
#pragma unroll
    for (int it = 0; it < 4; it++) {
        uint4 a = *(const uint4*)&A[(size_t)(bm + lrow[it]) * EMB + lc[it]];
        uint4 b = *(const uint4*)&B[(size_t)(bn + lrow[it]) * EMB + lc[it]];
        *(uint4*)&sm[lrow[it] * KW + lc[it] / 2] = a;
        *(uint4*)&sm[TILE_W + lrow[it] * KW + lc[it] / 2] = b;
    }
    __syncthreads();

    for (int ks = 0; ks < 16; ks++) {
        const int cur = ks & 1;
        const uint32_t* as = sm + cur * BUF_W + (wm * 32) * KW;
        const uint32_t* bs = sm + cur * BUF_W + TILE_W + (wn * 64) * KW;

        uint4 ra[4], rbv[4];
        if (ks + 1 < 16) {
#pragma unroll
            for (int it = 0; it < 4; it++) {
                ra[it]  = *(const uint4*)&A[(size_t)(bm + lrow[it]) * EMB + (ks + 1) * 64 + lc[it]];
                rbv[it] = *(const uint4*)&B[(size_t)(bn + lrow[it]) * EMB + (ks + 1) * 64 + lc[it]];
            }
        }

        // 4 k16 steps per BK=64 (word offsets 0, 8, 16, 24)
#pragma unroll
        for (int kk = 0; kk < 4; kk++) {
            const int k0 = kk * 8;
            uint32_t af[2][4];
#pragma unroll
            for (int mi = 0; mi < 2; mi++) {
                int r = mi * 16 + g;
                af[mi][0] = as[(r    ) * KW + k0 + tig];
                af[mi][1] = as[(r + 8) * KW + k0 + tig];
                af[mi][2] = as[(r    ) * KW + k0 + 4 + tig];
                af[mi][3] = as[(r + 8) * KW + k0 + 4 + tig];
            }
#pragma unroll
            for (int ni = 0; ni < 8; ni++) {
                uint32_t bf[2];
                int nr = ni * 8 + g;
                bf[0] = bs[nr * KW + k0 + tig];
                bf[1] = bs[nr * KW + k0 + 4 + tig];
                mma_f16(acc[0][ni], af[0], bf);
                mma_f16(acc[1][ni], af[1], bf);
            }
        }

        if (ks + 1 < 16) {
            const int nxt = cur ^ 1;
            uint32_t* an  = sm + nxt * BUF_W;
            uint32_t* bnp = an + TILE_W;
#pragma unroll
            for (int it = 0; it < 4; it++) {
                *(uint4*)&an[lrow[it] * KW + lc[it] / 2]  = ra[it];
                *(uint4*)&bnp[lrow[it] * KW + lc[it] / 2] = rbv[it];
            }
            __syncthreads();
        }
    }

#pragma unroll
    for (int mi = 0; mi < 2; mi++) {
        int r0 = bm + wm * 32 + mi * 16 + g;
#pragma unroll
        for (int ni = 0; ni < 8; ni++) {
            int col = bn + wn * 64 + ni * 8 + 2 * tig;
            float b0 = 0.f, b1 = 0.f;
            if (bias) { b0 = bias[col]; b1 = bias[col + 1]; }
            float c0 = acc[mi][ni][0] + b0, c1 = acc[mi][ni][1] + b1;
            float c2 = acc[mi][ni][2] + b0, c3 = acc[mi][ni][3] + b1;
            if (OUTHALF) {
                __half* Ch = (__half*)Cptr;
                *(uint32_t*)&Ch[(size_t)r0 * EMB + col]       = pack_h2(c0, c1);
                *(uint32_t*)&Ch[(size_t)(r0 + 8) * EMB + col] = pack_h2(c2, c3);
            } else {
                float* Cf = (float*)Cptr;
                *(float2*)&Cf[(size_t)r0 * EMB + col]       = make_float2(c0, c1);
                *(float2*)&Cf[(size_t)(r0 + 8) * EMB + col] = make_float2(c2, c3);
            }
        }
    }
}

__global__ __launch_bounds__(256) void gemm_qkv(
    const __half* __restrict__ X,
    const __half* __restrict__ Wq, const __half* __restrict__ Wk,
    const __half* __restrict__ Wv,
    __half* __restrict__ Qo, __half* __restrict__ Ko, __half* __restrict__ Vo)
{
    extern __shared__ uint32_t sm[];
    const int wb = blockIdx.x >> 3;
    const int bn = (blockIdx.x & 7) * 128;
    const int bm = blockIdx.y * 128;
    const __half* B = (wb == 0) ? Wq : (wb == 1) ? Wk : Wv;
    __half*       C = (wb == 0) ? Qo : (wb == 1) ? Ko : Vo;
    gemm_h_body<true>(X, B, nullptr, C, bm, bn, sm);
}

__global__ __launch_bounds__(256) void gemm_out(
    const __half* __restrict__ A, const __half* __restrict__ W,
    const float* __restrict__ bias, float* __restrict__ C)
{
    extern __shared__ uint32_t sm[];
    gemm_h_body<false>(A, W, bias, C, blockIdx.y * 128, blockIdx.x * 128, sm);
}

// ---------------------------------------------------------------------------
// Flash attention (causal), fp16 mma + polynomial exp2 softmax. All I/O fp16.
// Smem stride AW=36 words: frag address 4g+tig -> conflict-free. (R9 proven.)
// ---------------------------------------------------------------------------
#define AW 36

__global__ __launch_bounds__(256, 2) void attn_mma(
    const __half* __restrict__ Q, const __half* __restrict__ K,
    const __half* __restrict__ V, __half* __restrict__ O)
{
    __shared__ __align__(16) uint32_t KsW[64 * AW];
    __shared__ __align__(16) uint32_t VtW[64 * AW];
    __shared__ __align__(16) uint32_t PsW[128 * AW];

    const int tid  = threadIdx.x;
    const int lane = tid & 31, w = tid >> 5;
    const int g    = lane >> 2, tig = lane & 3;
    const int qt   = 15 - blockIdx.x;
    const int bh   = blockIdx.y;
    const int b    = bh >> 4, h = bh & 15;
    const size_t base  = (size_t)b * TS * EMB + (size_t)h * HD;
    const int    qbase = qt * 128;

#pragma unroll
    for (int it = 0; it < 4; it++) {
        int v = tid + it * 256;
        int row = v >> 3, c = v & 7;
        uint4 t = *(const uint4*)&Q[base + (size_t)(qbase + row) * EMB + c * 8];
        *(uint4*)&PsW[row * AW + c * 4] = t;
    }
    __syncthreads();

    uint32_t qa[4][4];
    {
        const int r0 = w * 16 + g;
#pragma unroll
        for (int kc = 0; kc < 4; kc++) {
            qa[kc][0] = PsW[(r0    ) * AW + kc * 8 + tig];
            qa[kc][1] = PsW[(r0 + 8) * AW + kc * 8 + tig];
            qa[kc][2] = PsW[(r0    ) * AW + kc * 8 + 4 + tig];
            qa[kc][3] = PsW[(r0 + 8) * AW + kc * 8 + 4 + tig];
        }
    }
    __syncthreads();

    float m0 = -1e30f, m1 = -1e30f, l0 = 0.f, l1 = 0.f;
    float o[8][4];
#pragma unroll
    for (int ni = 0; ni < 8; ni++)
#pragma unroll
        for (int j = 0; j < 4; j++) o[ni][j] = 0.f;

    const float scale2 = 0.125f * 1.44269504089f;
    const int nkt = 2 * qt + 2;
    const int qrow_max = qbase + w * 16 + 15;

    for (int kt = 0; kt < nkt; kt++) {
        __syncthreads();
#pragma unroll
        for (int it = 0; it < 2; it++) {
            int v = tid + it * 256;
            int row = v >> 3, c = v & 7;
            uint4 t = *(const uint4*)&K[base + (size_t)(kt * 64 + row) * EMB + c * 8];
            *(uint4*)&KsW[row * AW + c * 4] = t;
        }
#pragma unroll
        for (int it = 0; it < 2; it++) {
            int u  = tid + it * 256;
            int kp = u & 31, c4 = (u >> 5) * 4;
            const __half* va = &V[base + (size_t)(kt * 64 + 2 * kp) * EMB + c4];
            uint2 fa = *(const uint2*)va;
            uint2 fb = *(const uint2*)(va + EMB);
            VtW[(c4 + 0) * AW + kp] = prm(fa.x, fb.x, 0x5410);
            VtW[(c4 + 1) * AW + kp] = prm(fa.x, fb.x, 0x7632);
            VtW[(c4 + 2) * AW + kp] = prm(fa.y, fb.y, 0x5410);
            VtW[(c4 + 3) * AW + kp] = prm(fa.y, fb.y, 0x7632);
        }
        __syncthreads();

        if (kt * 64 > qrow_max) continue;

        float sc[8][4];
#pragma unroll
        for (int ni = 0; ni < 8; ni++) {
            sc[ni][0] = sc[ni][1] = sc[ni][2] = sc[ni][3] = 0.f;
            int nr = ni * 8 + g;
#pragma unroll
            for (int kc = 0; kc < 4; kc++) {
                uint32_t bf[2];
                bf[0] = KsW[nr * AW + kc * 8 + tig];
                bf[1] = KsW[nr * AW + kc * 8 + 4 + tig];
                mma_f16(sc[ni], qa[kc], bf);
            }
        }

        const bool diag = (kt * 64 + 63 > qbase + w * 16);
        const int qg0 = qbase + w * 16 + g, qg1 = qg0 + 8;
#pragma unroll
        for (int ni = 0; ni < 8; ni++) {
#pragma unroll
            for (int j = 0; j < 4; j++) sc[ni][j] *= scale2;
            if (diag) {
                int kg = kt * 64 + ni * 8 + 2 * tig;
                if (kg     > qg0) sc[ni][0] = -1e30f;
                if (kg + 1 > qg0) sc[ni][1] = -1e30f;
                if (kg     > qg1) sc[ni][2] = -1e30f;
                if (kg + 1 > qg1) sc[ni][3] = -1e30f;
            }
        }

        float rm0 = -1e30f, rm1 = -1e30f;
#pragma unroll
        for (int ni = 0; ni < 8; ni++) {
            rm0 = fmaxf(rm0, fmaxf(sc[ni][0], sc[ni][1]));
            rm1 = fmaxf(rm1, fmaxf(sc[ni][2], sc[ni][3]));
        }
        rm0 = qmax(rm0); rm1 = qmax(rm1);
        float mn0 = fmaxf(m0, rm0), mn1 = fmaxf(m1, rm1);
        float a0 = exp2p(m0 - mn0), a1 = exp2p(m1 - mn1);
        m0 = mn0; m1 = mn1;
#pragma unroll
        for (int ni = 0; ni < 8; ni++) {
            o[ni][0] *= a0; o[ni][1] *= a0;
            o[ni][2] *= a1; o[ni][3] *= a1;
        }
        float s0 = 0.f, s1 = 0.f;
        const int pr0 = w * 16 + g;
#pragma unroll
        for (int ni = 0; ni < 8; ni++) {
            float p0 = exp2p(sc[ni][0] - mn0);
            float p1 = exp2p(sc[ni][1] - mn0);
            float p2 = exp2p(sc[ni][2] - mn1);
            float p3 = exp2p(sc[ni][3] - mn1);
            s0 += p0 + p1; s1 += p2 + p3;
            PsW[(pr0    ) * AW + ni * 4 + tig] = pack_h2(p0, p1);
            PsW[(pr0 + 8) * AW + ni * 4 + tig] = pack_h2(p2, p3);
        }
        l0 = l0 * a0 + qsum(s0);
        l1 = l1 * a1 + qsum(s1);
        __syncwarp();

#pragma unroll
        for (int kc = 0; kc < 4; kc++) {
            uint32_t pa[4];
            pa[0] = PsW[(pr0    ) * AW + kc * 8 + tig];
            pa[1] = PsW[(pr0 + 8) * AW + kc * 8 + tig];
            pa[2] = PsW[(pr0    ) * AW + kc * 8 + 4 + tig];
            pa[3] = PsW[(pr0 + 8) * AW + kc * 8 + 4 + tig];
#pragma unroll
            for (int nd = 0; nd < 8; nd++) {
                uint32_t bf[2];
                int dr = nd * 8 + g;
                bf[0] = VtW[dr * AW + kc * 8 + tig];
                bf[1] = VtW[dr * AW + kc * 8 + 4 + tig];
                mma_f16(o[nd], pa, bf);
            }
        }
        __syncwarp();
    }

    const float inv0 = 1.f / l0, inv1 = 1.f / l1;
    const int q0 = qbase + w * 16 + g;
#pragma unroll
    for (int nd = 0; nd < 8; nd++) {
        int col = nd * 8 + 2 * tig;
        *(uint32_t*)&O[base + (size_t)q0 * EMB + col] =
            pack_h2(o[nd][0] * inv0, o[nd][1] * inv0);
        *(uint32_t*)&O[base + (size_t)(q0 + 8) * EMB + col] =
            pack_h2(o[nd][2] * inv1, o[nd][3] * inv1);
    }
}

// ---------------------------------------------------------------------------
extern "C" void kernel_launch(void* const* d_in, const int* in_sizes, int n_in,
                              void* d_out, int out_size)
{
    const float* x  = (const float*)d_in[0];
    // d_in[1] = mask (exact causal tril) -- applied analytically
    const float* Wq = (const float*)d_in[2];
    const float* Wk = (const float*)d_in[3];
    const float* Wv = (const float*)d_in[4];
    const float* Wo = (const float*)d_in[5];
    const float* bo = (const float*)d_in[6];
    float* out = (float*)d_out;

    __half *Qh, *Kh, *Vh, *Ah, *Xh, *Wqh, *Wkh, *Wvh, *Woh;
    cudaGetSymbolAddress((void**)&Qh, g_Qh);
    cudaGetSymbolAddress((void**)&Kh, g_Kh);
    cudaGetSymbolAddress((void**)&Vh, g_Vh);
    cudaGetSymbolAddress((void**)&Ah, g_Ah);
    cudaGetSymbolAddress((void**)&Xh, g_Xh);
    cudaGetSymbolAddress((void**)&Wqh, g_Wqh);
    cudaGetSymbolAddress((void**)&Wkh, g_Wkh);
    cudaGetSymbolAddress((void**)&Wvh, g_Wvh);
    cudaGetSymbolAddress((void**)&Woh, g_Woh);

    static bool attr_set = false;
    if (!attr_set) {
        cudaFuncSetAttribute(gemm_qkv, cudaFuncAttributeMaxDynamicSharedMemorySize, GEMM_SMEM);
        cudaFuncSetAttribute(gemm_out, cudaFuncAttributeMaxDynamicSharedMemorySize, GEMM_SMEM);
        attr_set = true;
    }

    // Prepass: 8M elements, 8 per thread -> 4096 blocks.
    const size_t total = (size_t)ROWS * EMB + 4 * (size_t)EMB * EMB;
    cvt_all<<<(int)(total / (256 * 8)), 256>>>(x, Wq, Wk, Wv, Wo,
                                               Xh, Wqh, Wkh, Wvh, Woh);

    dim3 qkvgrid(24, ROWS / 128);       // (24, 32)
    gemm_qkv<<<qkvgrid, 256, GEMM_SMEM>>>(Xh, Wqh, Wkh, Wvh, Qh, Kh, Vh);

    dim3 agrid(16, 2 * NHEADS);         // (16, 32)
    attn_mma<<<agrid, 256>>>(Qh, Kh, Vh, Ah);

    dim3 ogrid(EMB / 128, ROWS / 128);  // (8, 32)
    gemm_out<<<ogrid, 256, GEMM_SMEM>>>(Ah, Woh, bo, out);
}

// round 11
// speedup vs baseline: 1.4522x; 1.1754x over previous
#include <cuda_runtime.h>
#include <cuda_bf16.h>
#include <cuda_fp16.h>
#include <cstdint>

// Problem: MaskedSelfAttention  B=2, S=2048, E=1024, H=16, D=64, causal.
// R11: attention gets cp.async double-buffered K/V (straight-row smem) +
//      ldmatrix fragment loads (V transposed at consume time via .trans).
//      GEMMs/prepass unchanged from R10. Arithmetic identical -> rel_err canary.

#define TS   2048
#define EMB  1024
#define NHEADS 16
#define HD   64
#define ROWS (2*TS)

__device__ __half g_Qh[ROWS*EMB];
__device__ __half g_Kh[ROWS*EMB];
__device__ __half g_Vh[ROWS*EMB];
__device__ __half g_Ah[ROWS*EMB];
__device__ __half g_Xh[ROWS*EMB];
__device__ __half g_Wqh[EMB*EMB];
__device__ __half g_Wkh[EMB*EMB];
__device__ __half g_Wvh[EMB*EMB];
__device__ __half g_Woh[EMB*EMB];

__device__ __forceinline__ void mma_f16(float* d, const uint32_t* a, const uint32_t* b) {
    asm volatile(
        "mma.sync.aligned.m16n8k16.row.col.f32.f16.f16.f32 "
        "{%0,%1,%2,%3}, {%4,%5,%6,%7}, {%8,%9}, {%0,%1,%2,%3};"
        : "+f"(d[0]), "+f"(d[1]), "+f"(d[2]), "+f"(d[3])
        : "r"(a[0]), "r"(a[1]), "r"(a[2]), "r"(a[3]), "r"(b[0]), "r"(b[1]));
}

__device__ __forceinline__ uint32_t pack_h2(float x, float y) {
    __half2 h = __floats2half2_rn(x, y);
    return *(uint32_t*)&h;
}

__device__ __forceinline__ void ldm_x4(uint32_t& r0, uint32_t& r1,
                                       uint32_t& r2, uint32_t& r3, uint32_t addr) {
    asm volatile("ldmatrix.sync.aligned.m8n8.x4.shared.b16 {%0,%1,%2,%3}, [%4];"
        : "=r"(r0), "=r"(r1), "=r"(r2), "=r"(r3) : "r"(addr));
}
__device__ __forceinline__ void ldm_x4_t(uint32_t& r0, uint32_t& r1,
                                         uint32_t& r2, uint32_t& r3, uint32_t addr) {
    asm volatile("ldmatrix.sync.aligned.m8n8.x4.trans.shared.b16 {%0,%1,%2,%3}, [%4];"
        : "=r"(r0), "=r"(r1), "=r"(r2), "=r"(r3) : "r"(addr));
}

__device__ __forceinline__ void cp16(uint32_t saddr, const void* g) {
    asm volatile("cp.async.cg.shared.global [%0], [%1], 16;" :: "r"(saddr), "l"(g));
}
#define CP_COMMIT() asm volatile("cp.async.commit_group;" ::: "memory")
#define CP_WAIT0()  asm volatile("cp.async.wait_group 0;" ::: "memory")

// exp2 on the FMA/ALU pipes (no MUFU).
__device__ __forceinline__ float exp2p(float d) {
    d = fmaxf(d, -120.f);
    float t = d + 12582912.f;
    float f = d - (t - 12582912.f);
    uint32_t e = (__float_as_uint(t) + (127u - 0x4B400000u)) << 23;
    float p = 1.3333558146e-3f;
    p = fmaf(p, f, 9.6181291076e-3f);
    p = fmaf(p, f, 5.5504108665e-2f);
    p = fmaf(p, f, 2.4022650696e-1f);
    p = fmaf(p, f, 6.9314718056e-1f);
    p = fmaf(p, f, 1.0f);
    return p * __uint_as_float(e);
}

__device__ __forceinline__ float qmax(float v) {
    v = fmaxf(v, __shfl_xor_sync(0xffffffffu, v, 1));
    v = fmaxf(v, __shfl_xor_sync(0xffffffffu, v, 2));
    return v;
}
__device__ __forceinline__ float qsum(float v) {
    v += __shfl_xor_sync(0xffffffffu, v, 1);
    v += __shfl_xor_sync(0xffffffffu, v, 2);
    return v;
}

// ---------------------------------------------------------------------------
// Prepass: convert x (4M) + 4 weights (1M each) fp32 -> fp16. 8 elems/thread.
// ---------------------------------------------------------------------------
__global__ __launch_bounds__(256) void cvt_all(
    const float* __restrict__ X,
    const float* __restrict__ Wq, const float* __restrict__ Wk,
    const float* __restrict__ Wv, const float* __restrict__ Wo,
    __half* __restrict__ Xh, __half* __restrict__ Wqh, __half* __restrict__ Wkh,
    __half* __restrict__ Wvh, __half* __restrict__ Woh)
{
    size_t i = ((size_t)blockIdx.x * 256 + threadIdx.x) * 8;
    const float* src; __half* dst; size_t off;
    const size_t NX = (size_t)ROWS * EMB, NW = (size_t)EMB * EMB;
    if (i < NX)               { src = X;  dst = Xh;  off = i; }
    else if (i < NX + NW)     { src = Wq; dst = Wqh; off = i - NX; }
    else if (i < NX + 2*NW)   { src = Wk; dst = Wkh; off = i - NX - NW; }
    else if (i < NX + 3*NW)   { src = Wv; dst = Wvh; off = i - NX - 2*NW; }
    else                      { src = Wo; dst = Woh; off = i - NX - 3*NW; }
    float4 a = *(const float4*)&src[off];
    float4 b = *(const float4*)&src[off + 4];
    uint4 u = make_uint4(pack_h2(a.x, a.y), pack_h2(a.z, a.w),
                         pack_h2(b.x, b.y), pack_h2(b.z, b.w));
    *(uint4*)&dst[off] = u;
}

// ---------------------------------------------------------------------------
// fp16 GEMM (R10, proven): CTA 128x128, BK=64, 8 warps, double-buffered smem.
// ---------------------------------------------------------------------------
#define KW 36
#define TILE_W (128 * KW)
#define BUF_W  (2 * TILE_W)
#define GEMM_SMEM (2 * BUF_W * 4)

template <bool OUTHALF>
__device__ __forceinline__ void gemm_h_body(
    const __half* __restrict__ A, const __half* __restrict__ B,
    const float* __restrict__ bias, void* __restrict__ Cptr,
    int bm, int bn, uint32_t* sm)
{
    const int tid  = threadIdx.x;
    const int lane = tid & 31, warp = tid >> 5;
    const int g    = lane >> 2, tig = lane & 3;
    const int wm   = warp >> 1, wn = warp & 1;

    int lrow[4], lc[4];
#pragma unroll
    for (int it = 0; it < 4; it++) {
        int v = tid + it * 256;
        lrow[it] = v >> 3;
        lc[it]   = (v & 7) * 8;
    }

    float acc[2][8][4];
#pragma unroll
    for (int mi = 0; mi < 2; mi++)
#pragma unroll
        for (int ni = 0; ni < 8; ni++)
#pragma unroll
            for (int j = 0; j < 4; j++) acc[mi][ni][j] = 0.f;

#pragma unroll
    for (int it = 0; it < 4; it++) {
        uint4 a = *(const uint4*)&A[(size_t)(bm + lrow[it]) * EMB + lc[it]];
        uint4 b = *(const uint4*)&B[(size_t)(bn + lrow[it]) * EMB + lc[it]];
        *(uint4*)&sm[lrow[it] * KW + lc[it] / 2] = a;
        *(uint4*)&sm[TILE_W + lrow[it] * KW + lc[it] / 2] = b;
    }
    __syncthreads();

    for (int ks = 0; ks < 16; ks++) {
        const int cur = ks & 1;
        const uint32_t* as = sm + cur * BUF_W + (wm * 32) * KW;
        const uint32_t* bs = sm + cur * BUF_W + TILE_W + (wn * 64) * KW;

        uint4 ra[4], rbv[4];
        if (ks + 1 < 16) {
#pragma unroll
            for (int it = 0; it < 4; it++) {
                ra[it]  = *(const uint4*)&A[(size_t)(bm + lrow[it]) * EMB + (ks + 1) * 64 + lc[it]];
                rbv[it] = *(const uint4*)&B[(size_t)(bn + lrow[it]) * EMB + (ks + 1) * 64 + lc[it]];
            }
        }

#pragma unroll
        for (int kk = 0; kk < 4; kk++) {
            const int k0 = kk * 8;
            uint32_t af[2][4];
#pragma unroll
            for (int mi = 0; mi < 2; mi++) {
                int r = mi * 16 + g;
                af[mi][0] = as[(r    ) * KW + k0 + tig];
                af[mi][1] = as[(r + 8) * KW + k0 + tig];
                af[mi][2] = as[(r    ) * KW + k0 + 4 + tig];
                af[mi][3] = as[(r + 8) * KW + k0 + 4 + tig];
            }
#pragma unroll
            for (int ni = 0; ni < 8; ni++) {
                uint32_t bf[2];
                int nr = ni * 8 + g;
                bf[0] = bs[nr * KW + k0 + tig];
                bf[1] = bs[nr * KW + k0 + 4 + tig];
                mma_f16(acc[0][ni], af[0], bf);
                mma_f16(acc[1][ni], af[1], bf);
            }
        }

        if (ks + 1 < 16) {
            const int nxt = cur ^ 1;
            uint32_t* an  = sm + nxt * BUF_W;
            uint32_t* bnp = an + TILE_W;
#pragma unroll
            for (int it = 0; it < 4; it++) {
                *(uint4*)&an[lrow[it] * KW + lc[it] / 2]  = ra[it];
                *(uint4*)&bnp[lrow[it] * KW + lc[it] / 2] = rbv[it];
            }
            __syncthreads();
        }
    }

#pragma unroll
    for (int mi = 0; mi < 2; mi++) {
        int r0 = bm + wm * 32 + mi * 16 + g;
#pragma unroll
        for (int ni = 0; ni < 8; ni++) {
            int col = bn + wn * 64 + ni * 8 + 2 * tig;
            float b0 = 0.f, b1 = 0.f;
            if (bias) { b0 = bias[col]; b1 = bias[col + 1]; }
            float c0 = acc[mi][ni][0] + b0, c1 = acc[mi][ni][1] + b1;
            float c2 = acc[mi][ni][2] + b0, c3 = acc[mi][ni][3] + b1;
            if (OUTHALF) {
                __half* Ch = (__half*)Cptr;
                *(uint32_t*)&Ch[(size_t)r0 * EMB + col]       = pack_h2(c0, c1);
                *(uint32_t*)&Ch[(size_t)(r0 + 8) * EMB + col] = pack_h2(c2, c3);
            } else {
                float* Cf = (float*)Cptr;
                *(float2*)&Cf[(size_t)r0 * EMB + col]       = make_float2(c0, c1);
                *(float2*)&Cf[(size_t)(r0 + 8) * EMB + col] = make_float2(c2, c3);
            }
        }
    }
}

__global__ __launch_bounds__(256) void gemm_qkv(
    const __half* __restrict__ X,
    const __half* __restrict__ Wq, const __half* __restrict__ Wk,
    const __half* __restrict__ Wv,
    __half* __restrict__ Qo, __half* __restrict__ Ko, __half* __restrict__ Vo)
{
    extern __shared__ uint32_t sm[];
    const int wb = blockIdx.x >> 3;
    const int bn = (blockIdx.x & 7) * 128;
    const int bm = blockIdx.y * 128;
    const __half* B = (wb == 0) ? Wq : (wb == 1) ? Wk : Wv;
    __half*       C = (wb == 0) ? Qo : (wb == 1) ? Ko : Vo;
    gemm_h_body<true>(X, B, nullptr, C, bm, bn, sm);
}

__global__ __launch_bounds__(256) void gemm_out(
    const __half* __restrict__ A, const __half* __restrict__ W,
    const float* __restrict__ bias, float* __restrict__ C)
{
    extern __shared__ uint32_t sm[];
    gemm_h_body<false>(A, W, bias, C, blockIdx.y * 128, blockIdx.x * 128, sm);
}

// ---------------------------------------------------------------------------
// Flash attention (causal), fp16 mma + poly exp2. cp.async 2-stage K/V,
// ldmatrix fragments. All I/O fp16. Row stride AW=36 words (conflict-free).
// Dynamic smem layout (bytes): K stages [0, 18432), V stages [18432, 36864),
// P [36864, 55296).
// ---------------------------------------------------------------------------
#define AW 36
#define KV_STAGE_B (64 * AW * 4)           // 9216
#define PS_OFF_B   (4 * KV_STAGE_B)        // 36864
#define ATTN_SMEM  (PS_OFF_B + 128 * AW * 4)   // 55296

__global__ __launch_bounds__(256, 2) void attn_mma(
    const __half* __restrict__ Q, const __half* __restrict__ K,
    const __half* __restrict__ V, __half* __restrict__ O)
{
    extern __shared__ __align__(16) uint32_t smw[];
    uint32_t* PsW = smw + PS_OFF_B / 4;
    const uint32_t smb = (uint32_t)__cvta_generic_to_shared(smw);

    const int tid  = threadIdx.x;
    const int lane = tid & 31, w = tid >> 5;
    const int g    = lane >> 2, tig = lane & 3;
    const int qt   = 15 - blockIdx.x;
    const int bh   = blockIdx.y;
    const int b    = bh >> 4, h = bh & 15;
    const size_t base  = (size_t)b * TS * EMB + (size_t)h * HD;
    const int    qbase = qt * 128;
    const int    nkt   = 2 * qt + 2;

    // ldmatrix per-thread address components
    const int lm_t = lane & 7, lm_sel = lane >> 3;

    // ---- Prologue: issue cp.async for tile 0 -> stage 0.
    {
#pragma unroll
        for (int it = 0; it < 2; it++) {
            int v = tid + it * 256;
            int row = v >> 3, c = v & 7;
            cp16(smb + (row * AW + c * 4) * 4,
                 &K[base + (size_t)(row) * EMB + c * 8]);
        }
#pragma unroll
        for (int it = 0; it < 2; it++) {
            int v = tid + it * 256;
            int row = v >> 3, c = v & 7;
            cp16(smb + 2 * KV_STAGE_B + (row * AW + c * 4) * 4,
                 &V[base + (size_t)(row) * EMB + c * 8]);
        }
        CP_COMMIT();
    }

    // ---- Stage Q tile into Ps, lift to fragments.
#pragma unroll
    for (int it = 0; it < 4; it++) {
        int v = tid + it * 256;
        int row = v >> 3, c = v & 7;
        uint4 t = *(const uint4*)&Q[base + (size_t)(qbase + row) * EMB + c * 8];
        *(uint4*)&PsW[row * AW + c * 4] = t;
    }
    __syncthreads();

    uint32_t qa[4][4];
    {
        const int r0 = w * 16 + g;
#pragma unroll
        for (int kc = 0; kc < 4; kc++) {
            qa[kc][0] = PsW[(r0    ) * AW + kc * 8 + tig];
            qa[kc][1] = PsW[(r0 + 8) * AW + kc * 8 + tig];
            qa[kc][2] = PsW[(r0    ) * AW + kc * 8 + 4 + tig];
            qa[kc][3] = PsW[(r0 + 8) * AW + kc * 8 + 4 + tig];
        }
    }

    float m0 = -1e30f, m1 = -1e30f, l0 = 0.f, l1 = 0.f;
    float o[8][4];
#pragma unroll
    for (int ni = 0; ni < 8; ni++)
#pragma unroll
        for (int j = 0; j < 4; j++) o[ni][j] = 0.f;

    const float scale2 = 0.125f * 1.44269504089f;
    const int qrow_max = qbase + w * 16 + 15;

    for (int kt = 0; kt < nkt; kt++) {
        CP_WAIT0();          // tile kt's K/V landed
        __syncthreads();     // + everyone done with stage (kt+1)&1 (read at kt-1)

        // Issue next tile into the other stage (overlaps this tile's compute).
        if (kt + 1 < nkt) {
            const int ns = (kt + 1) & 1;
#pragma unroll
            for (int it = 0; it < 2; it++) {
                int v = tid + it * 256;
                int row = v >> 3, c = v & 7;
                cp16(smb + ns * KV_STAGE_B + (row * AW + c * 4) * 4,
                     &K[base + (size_t)((kt + 1) * 64 + row) * EMB + c * 8]);
            }
#pragma unroll
            for (int it = 0; it < 2; it++) {
                int v = tid + it * 256;
                int row = v >> 3, c = v & 7;
                cp16(smb + 2 * KV_STAGE_B + ns * KV_STAGE_B + (row * AW + c * 4) * 4,
                     &V[base + (size_t)((kt + 1) * 64 + row) * EMB + c * 8]);
            }
            CP_COMMIT();
        }

        if (kt * 64 > qrow_max) continue;   // warp fully masked

        const uint32_t KsS = smb + (kt & 1) * KV_STAGE_B;
        const uint32_t VsS = smb + 2 * KV_STAGE_B + (kt & 1) * KV_STAGE_B;

        // ---- Scores: B-frags via ldmatrix.x4 (non-trans) from K rows.
        float sc[8][4];
#pragma unroll
        for (int ni = 0; ni < 8; ni++)
            sc[ni][0] = sc[ni][1] = sc[ni][2] = sc[ni][3] = 0.f;
#pragma unroll
        for (int np = 0; np < 4; np++) {
#pragma unroll
            for (int kc = 0; kc < 4; kc++) {
                int row  = np * 16 + ((lm_sel >> 1) << 3) + lm_t;
                int hoff = kc * 16 + ((lm_sel & 1) << 3);
                uint32_t b0, b1, b2, b3;
                ldm_x4(b0, b1, b2, b3, KsS + row * (AW * 4) + hoff * 2);
                uint32_t bfA[2] = {b0, b1}, bfB[2] = {b2, b3};
                mma_f16(sc[2 * np],     qa[kc], bfA);
                mma_f16(sc[2 * np + 1], qa[kc], bfB);
            }
        }

        // ---- Scale + causal mask
        const bool diag = (kt * 64 + 63 > qbase + w * 16);
        const int qg0 = qbase + w * 16 + g, qg1 = qg0 + 8;
#pragma unroll
        for (int ni = 0; ni < 8; ni++) {
#pragma unroll
            for (int j = 0; j < 4; j++) sc[ni][j] *= scale2;
            if (diag) {
                int kg = kt * 64 + ni * 8 + 2 * tig;
                if (kg     > qg0) sc[ni][0] = -1e30f;
                if (kg + 1 > qg0) sc[ni][1] = -1e30f;
                if (kg     > qg1) sc[ni][2] = -1e30f;
                if (kg + 1 > qg1) sc[ni][3] = -1e30f;
            }
        }

        // ---- Online softmax (base-2), P -> Ps
        float rm0 = -1e30f, rm1 = -1e30f;
#pragma unroll
        for (int ni = 0; ni < 8; ni++) {
            rm0 = fmaxf(rm0, fmaxf(sc[ni][0], sc[ni][1]));
            rm1 = fmaxf(rm1, fmaxf(sc[ni][2], sc[ni][3]));
        }
        rm0 = qmax(rm0); rm1 = qmax(rm1);
        float mn0 = fmaxf(m0, rm0), mn1 = fmaxf(m1, rm1);
        float a0 = exp2p(m0 - mn0), a1 = exp2p(m1 - mn1);
        m0 = mn0; m1 = mn1;
#pragma unroll
        for (int ni = 0; ni < 8; ni++) {
            o[ni][0] *= a0; o[ni][1] *= a0;
            o[ni][2] *= a1; o[ni][3] *= a1;
        }
        float s0 = 0.f, s1 = 0.f;
        const int pr0 = w * 16 + g;
#pragma unroll
        for (int ni = 0; ni < 8; ni++) {
            float p0 = exp2p(sc[ni][0] - mn0);
            float p1 = exp2p(sc[ni][1] - mn0);
            float p2 = exp2p(sc[ni][2] - mn1);
            float p3 = exp2p(sc[ni][3] - mn1);
            s0 += p0 + p1; s1 += p2 + p3;
            PsW[(pr0    ) * AW + ni * 4 + tig] = pack_h2(p0, p1);
            PsW[(pr0 + 8) * AW + ni * 4 + tig] = pack_h2(p2, p3);
        }
        l0 = l0 * a0 + qsum(s0);
        l1 = l1 * a1 + qsum(s1);
        __syncwarp();

        // ---- PV: B-frags via ldmatrix.x4.trans from V rows.
#pragma unroll
        for (int kc = 0; kc < 4; kc++) {
            uint32_t pa[4];
            pa[0] = PsW[(pr0    ) * AW + kc * 8 + tig];
            pa[1] = PsW[(pr0 + 8) * AW + kc * 8 + tig];
            pa[2] = PsW[(pr0    ) * AW + kc * 8 + 4 + tig];
            pa[3] = PsW[(pr0 + 8) * AW + kc * 8 + 4 + tig];
#pragma unroll
            for (int ndp = 0; ndp < 4; ndp++) {
                int row  = kc * 16 + ((lm_sel & 1) << 3) + lm_t;
                int hoff = ndp * 16 + ((lm_sel >> 1) << 3);
                uint32_t b0, b1, b2, b3;
                ldm_x4_t(b0, b1, b2, b3, VsS + row * (AW * 4) + hoff * 2);
                uint32_t bfA[2] = {b0, b1}, bfB[2] = {b2, b3};
                mma_f16(o[2 * ndp],     pa, bfA);
                mma_f16(o[2 * ndp + 1], pa, bfB);
            }
        }
        __syncwarp();
    }

    // ---- Normalize + store (half)
    const float inv0 = 1.f / l0, inv1 = 1.f / l1;
    const int q0 = qbase + w * 16 + g;
#pragma unroll
    for (int nd = 0; nd < 8; nd++) {
        int col = nd * 8 + 2 * tig;
        *(uint32_t*)&O[base + (size_t)q0 * EMB + col] =
            pack_h2(o[nd][0] * inv0, o[nd][1] * inv0);
        *(uint32_t*)&O[base + (size_t)(q0 + 8) * EMB + col] =
            pack_h2(o[nd][2] * inv1, o[nd][3] * inv1);
    }
}

// ---------------------------------------------------------------------------
extern "C" void kernel_launch(void* const* d_in, const int* in_sizes, int n_in,
                              void* d_out, int out_size)
{
    const float* x  = (const float*)d_in[0];
    // d_in[1] = mask (exact causal tril) -- applied analytically
    const float* Wq = (const float*)d_in[2];
    const float* Wk = (const float*)d_in[3];
    const float* Wv = (const float*)d_in[4];
    const float* Wo = (const float*)d_in[5];
    const float* bo = (const float*)d_in[6];
    float* out = (float*)d_out;

    __half *Qh, *Kh, *Vh, *Ah, *Xh, *Wqh, *Wkh, *Wvh, *Woh;
    cudaGetSymbolAddress((void**)&Qh, g_Qh);
    cudaGetSymbolAddress((void**)&Kh, g_Kh);
    cudaGetSymbolAddress((void**)&Vh, g_Vh);
    cudaGetSymbolAddress((void**)&Ah, g_Ah);
    cudaGetSymbolAddress((void**)&Xh, g_Xh);
    cudaGetSymbolAddress((void**)&Wqh, g_Wqh);
    cudaGetSymbolAddress((void**)&Wkh, g_Wkh);
    cudaGetSymbolAddress((void**)&Wvh, g_Wvh);
    cudaGetSymbolAddress((void**)&Woh, g_Woh);

    cudaFuncSetAttribute(gemm_qkv, cudaFuncAttributeMaxDynamicSharedMemorySize, GEMM_SMEM);
    cudaFuncSetAttribute(gemm_out, cudaFuncAttributeMaxDynamicSharedMemorySize, GEMM_SMEM);
    cudaFuncSetAttribute(attn_mma, cudaFuncAttributeMaxDynamicSharedMemorySize, ATTN_SMEM);

    const size_t total = (size_t)ROWS * EMB + 4 * (size_t)EMB * EMB;
    cvt_all<<<(int)(total / (256 * 8)), 256>>>(x, Wq, Wk, Wv, Wo,
                                               Xh, Wqh, Wkh, Wvh, Woh);

    dim3 qkvgrid(24, ROWS / 128);       // (24, 32)
    gemm_qkv<<<qkvgrid, 256, GEMM_SMEM>>>(Xh, Wqh, Wkh, Wvh, Qh, Kh, Vh);

    dim3 agrid(16, 2 * NHEADS);         // (16, 32)
    attn_mma<<<agrid, 256, ATTN_SMEM>>>(Qh, Kh, Vh, Ah);

    dim3 ogrid(EMB / 128, ROWS / 128);  // (8, 32)
    gemm_out<<<ogrid, 256, GEMM_SMEM>>>(Ah, Woh, bo, out);
}

// round 12
// speedup vs baseline: 1.5282x; 1.0523x over previous
#include <cuda_runtime.h>
#include <cuda_bf16.h>
#include <cuda_fp16.h>
#include <cstdint>

// Problem: MaskedSelfAttention  B=2, S=2048, E=1024, H=16, D=64, causal.
// R12: GEMM mainloops get cp.async double-buffering (same transform that won
//      in attention at R11). Attention/prepass unchanged. rel_err canary
//      must stay 6.582877e-4.

#define TS   2048
#define EMB  1024
#define NHEADS 16
#define HD   64
#define ROWS (2*TS)

__device__ __half g_Qh[ROWS*EMB];
__device__ __half g_Kh[ROWS*EMB];
__device__ __half g_Vh[ROWS*EMB];
__device__ __half g_Ah[ROWS*EMB];
__device__ __half g_Xh[ROWS*EMB];
__device__ __half g_Wqh[EMB*EMB];
__device__ __half g_Wkh[EMB*EMB];
__device__ __half g_Wvh[EMB*EMB];
__device__ __half g_Woh[EMB*EMB];

__device__ __forceinline__ void mma_f16(float* d, const uint32_t* a, const uint32_t* b) {
    asm volatile(
        "mma.sync.aligned.m16n8k16.row.col.f32.f16.f16.f32 "
        "{%0,%1,%2,%3}, {%4,%5,%6,%7}, {%8,%9}, {%0,%1,%2,%3};"
        : "+f"(d[0]), "+f"(d[1]), "+f"(d[2]), "+f"(d[3])
        : "r"(a[0]), "r"(a[1]), "r"(a[2]), "r"(a[3]), "r"(b[0]), "r"(b[1]));
}

__device__ __forceinline__ uint32_t pack_h2(float x, float y) {
    __half2 h = __floats2half2_rn(x, y);
    return *(uint32_t*)&h;
}

__device__ __forceinline__ void ldm_x4(uint32_t& r0, uint32_t& r1,
                                       uint32_t& r2, uint32_t& r3, uint32_t addr) {
    asm volatile("ldmatrix.sync.aligned.m8n8.x4.shared.b16 {%0,%1,%2,%3}, [%4];"
        : "=r"(r0), "=r"(r1), "=r"(r2), "=r"(r3) : "r"(addr));
}
__device__ __forceinline__ void ldm_x4_t(uint32_t& r0, uint32_t& r1,
                                         uint32_t& r2, uint32_t& r3, uint32_t addr) {
    asm volatile("ldmatrix.sync.aligned.m8n8.x4.trans.shared.b16 {%0,%1,%2,%3}, [%4];"
        : "=r"(r0), "=r"(r1), "=r"(r2), "=r"(r3) : "r"(addr));
}

__device__ __forceinline__ void cp16(uint32_t saddr, const void* g) {
    asm volatile("cp.async.cg.shared.global [%0], [%1], 16;" :: "r"(saddr), "l"(g));
}
#define CP_COMMIT() asm volatile("cp.async.commit_group;" ::: "memory")
#define CP_WAIT0()  asm volatile("cp.async.wait_group 0;" ::: "memory")

// exp2 on the FMA/ALU pipes (no MUFU).
__device__ __forceinline__ float exp2p(float d) {
    d = fmaxf(d, -120.f);
    float t = d + 12582912.f;
    float f = d - (t - 12582912.f);
    uint32_t e = (__float_as_uint(t) + (127u - 0x4B400000u)) << 23;
    float p = 1.3333558146e-3f;
    p = fmaf(p, f, 9.6181291076e-3f);
    p = fmaf(p, f, 5.5504108665e-2f);
    p = fmaf(p, f, 2.4022650696e-1f);
    p = fmaf(p, f, 6.9314718056e-1f);
    p = fmaf(p, f, 1.0f);
    return p * __uint_as_float(e);
}

__device__ __forceinline__ float qmax(float v) {
    v = fmaxf(v, __shfl_xor_sync(0xffffffffu, v, 1));
    v = fmaxf(v, __shfl_xor_sync(0xffffffffu, v, 2));
    return v;
}
__device__ __forceinline__ float qsum(float v) {
    v += __shfl_xor_sync(0xffffffffu, v, 1);
    v += __shfl_xor_sync(0xffffffffu, v, 2);
    return v;
}

// ---------------------------------------------------------------------------
// Prepass: convert x (4M) + 4 weights (1M each) fp32 -> fp16. 8 elems/thread.
// ---------------------------------------------------------------------------
__global__ __launch_bounds__(256) void cvt_all(
    const float* __restrict__ X,
    const float* __restrict__ Wq, const float* __restrict__ Wk,
    const float* __restrict__ Wv, const float* __restrict__ Wo,
    __half* __restrict__ Xh, __half* __restrict__ Wqh, __half* __restrict__ Wkh,
    __half* __restrict__ Wvh, __half* __restrict__ Woh)
{
    size_t i = ((size_t)blockIdx.x * 256 + threadIdx.x) * 8;
    const float* src; __half* dst; size_t off;
    const size_t NX = (size_t)ROWS * EMB, NW = (size_t)EMB * EMB;
    if (i < NX)               { src = X;  dst = Xh;  off = i; }
    else if (i < NX + NW)     { src = Wq; dst = Wqh; off = i - NX; }
    else if (i < NX + 2*NW)   { src = Wk; dst = Wkh; off = i - NX - NW; }
    else if (i < NX + 3*NW)   { src = Wv; dst = Wvh; off = i - NX - 2*NW; }
    else                      { src = Wo; dst = Woh; off = i - NX - 3*NW; }
    float4 a = *(const float4*)&src[off];
    float4 b = *(const float4*)&src[off + 4];
    uint4 u = make_uint4(pack_h2(a.x, a.y), pack_h2(a.z, a.w),
                         pack_h2(b.x, b.y), pack_h2(b.z, b.w));
    *(uint4*)&dst[off] = u;
}

// ---------------------------------------------------------------------------
// fp16 GEMM: CTA 128x128, BK=64, 8 warps, cp.async 2-stage double buffer.
// Row stride KW=36 words -> frag address 4g+tig conflict-free.
// ---------------------------------------------------------------------------
#define KW 36
#define TILE_W (128 * KW)
#define BUF_W  (2 * TILE_W)
#define GEMM_SMEM (2 * BUF_W * 4)   // 73728 B

template <bool OUTHALF>
__device__ __forceinline__ void gemm_h_body(
    const __half* __restrict__ A, const __half* __restrict__ B,
    const float* __restrict__ bias, void* __restrict__ Cptr,
    int bm, int bn, uint32_t* sm)
{
    const uint32_t smb = (uint32_t)__cvta_generic_to_shared(sm);
    const int tid  = threadIdx.x;
    const int lane = tid & 31, warp = tid >> 5;
    const int g    = lane >> 2, tig = lane & 3;
    const int wm   = warp >> 1, wn = warp & 1;

    int lrow[4], lc[4];
#pragma unroll
    for (int it = 0; it < 4; it++) {
        int v = tid + it * 256;
        lrow[it] = v >> 3;
        lc[it]   = (v & 7) * 8;      // half offset within BK=64
    }

    float acc[2][8][4];
#pragma unroll
    for (int mi = 0; mi < 2; mi++)
#pragma unroll
        for (int ni = 0; ni < 8; ni++)
#pragma unroll
            for (int j = 0; j < 4; j++) acc[mi][ni][j] = 0.f;

    // Prologue: issue cp.async for tile 0 -> stage 0.
#pragma unroll
    for (int it = 0; it < 4; it++) {
        uint32_t so = (lrow[it] * KW + lc[it] / 2) * 4;
        cp16(smb + so,              &A[(size_t)(bm + lrow[it]) * EMB + lc[it]]);
        cp16(smb + TILE_W * 4 + so, &B[(size_t)(bn + lrow[it]) * EMB + lc[it]]);
    }
    CP_COMMIT();

    for (int ks = 0; ks < 16; ks++) {
        const int cur = ks & 1;
        CP_WAIT0();          // tile ks landed
        __syncthreads();     // + all warps done reading stage cur^1 (iter ks-1)

        // Issue tile ks+1 into the other stage; overlaps this tile's MMAs.
        if (ks + 1 < 16) {
            const uint32_t sb2 = smb + (cur ^ 1) * BUF_W * 4;
#pragma unroll
            for (int it = 0; it < 4; it++) {
                uint32_t so = (lrow[it] * KW + lc[it] / 2) * 4;
                cp16(sb2 + so,              &A[(size_t)(bm + lrow[it]) * EMB + (ks + 1) * 64 + lc[it]]);
                cp16(sb2 + TILE_W * 4 + so, &B[(size_t)(bn + lrow[it]) * EMB + (ks + 1) * 64 + lc[it]]);
            }
            CP_COMMIT();
        }

        const uint32_t* as = sm + cur * BUF_W + (wm * 32) * KW;
        const uint32_t* bs = sm + cur * BUF_W + TILE_W + (wn * 64) * KW;

        // 4 k16 steps per BK=64 (word offsets 0, 8, 16, 24)
#pragma unroll
        for (int kk = 0; kk < 4; kk++) {
            const int k0 = kk * 8;
            uint32_t af[2][4];
#pragma unroll
            for (int mi = 0; mi < 2; mi++) {
                int r = mi * 16 + g;
                af[mi][0] = as[(r    ) * KW + k0 + tig];
                af[mi][1] = as[(r + 8) * KW + k0 + tig];
                af[mi][2] = as[(r    ) * KW + k0 + 4 + tig];
                af[mi][3] = as[(r + 8) * KW + k0 + 4 + tig];
            }
#pragma unroll
            for (int ni = 0; ni < 8; ni++) {
                uint32_t bf[2];
                int nr = ni * 8 + g;
                bf[0] = bs[nr * KW + k0 + tig];
                bf[1] = bs[nr * KW + k0 + 4 + tig];
                mma_f16(acc[0][ni], af[0], bf);
                mma_f16(acc[1][ni], af[1], bf);
            }
        }
    }

#pragma unroll
    for (int mi = 0; mi < 2; mi++) {
        int r0 = bm + wm * 32 + mi * 16 + g;
#pragma unroll
        for (int ni = 0; ni < 8; ni++) {
            int col = bn + wn * 64 + ni * 8 + 2 * tig;
            float b0 = 0.f, b1 = 0.f;
            if (bias) { b0 = bias[col]; b1 = bias[col + 1]; }
            float c0 = acc[mi][ni][0] + b0, c1 = acc[mi][ni][1] + b1;
            float c2 = acc[mi][ni][2] + b0, c3 = acc[mi][ni][3] + b1;
            if (OUTHALF) {
                __half* Ch = (__half*)Cptr;
                *(uint32_t*)&Ch[(size_t)r0 * EMB + col]       = pack_h2(c0, c1);
                *(uint32_t*)&Ch[(size_t)(r0 + 8) * EMB + col] = pack_h2(c2, c3);
            } else {
                float* Cf = (float*)Cptr;
                *(float2*)&Cf[(size_t)r0 * EMB + col]       = make_float2(c0, c1);
                *(float2*)&Cf[(size_t)(r0 + 8) * EMB + col] = make_float2(c2, c3);
            }
        }
    }
}

__global__ __launch_bounds__(256) void gemm_qkv(
    const __half* __restrict__ X,
    const __half* __restrict__ Wq, const __half* __restrict__ Wk,
    const __half* __restrict__ Wv,
    __half* __restrict__ Qo, __half* __restrict__ Ko, __half* __restrict__ Vo)
{
    extern __shared__ uint32_t sm[];
    const int wb = blockIdx.x >> 3;
    const int bn = (blockIdx.x & 7) * 128;
    const int bm = blockIdx.y * 128;
    const __half* B = (wb == 0) ? Wq : (wb == 1) ? Wk : Wv;
    __half*       C = (wb == 0) ? Qo : (wb == 1) ? Ko : Vo;
    gemm_h_body<true>(X, B, nullptr, C, bm, bn, sm);
}

__global__ __launch_bounds__(256) void gemm_out(
    const __half* __restrict__ A, const __half* __restrict__ W,
    const float* __restrict__ bias, float* __restrict__ C)
{
    extern __shared__ uint32_t sm[];
    gemm_h_body<false>(A, W, bias, C, blockIdx.y * 128, blockIdx.x * 128, sm);
}

// ---------------------------------------------------------------------------
// Flash attention (causal), fp16 mma + poly exp2. cp.async 2-stage K/V,
// ldmatrix fragments. All I/O fp16. Row stride AW=36 words. (R11 proven.)
// ---------------------------------------------------------------------------
#define AW 36
#define KV_STAGE_B (64 * AW * 4)
#define PS_OFF_B   (4 * KV_STAGE_B)
#define ATTN_SMEM  (PS_OFF_B + 128 * AW * 4)

__global__ __launch_bounds__(256, 2) void attn_mma(
    const __half* __restrict__ Q, const __half* __restrict__ K,
    const __half* __restrict__ V, __half* __restrict__ O)
{
    extern __shared__ __align__(16) uint32_t smw[];
    uint32_t* PsW = smw + PS_OFF_B / 4;
    const uint32_t smb = (uint32_t)__cvta_generic_to_shared(smw);

    const int tid  = threadIdx.x;
    const int lane = tid & 31, w = tid >> 5;
    const int g    = lane >> 2, tig = lane & 3;
    const int qt   = 15 - blockIdx.x;
    const int bh   = blockIdx.y;
    const int b    = bh >> 4, h = bh & 15;
    const size_t base  = (size_t)b * TS * EMB + (size_t)h * HD;
    const int    qbase = qt * 128;
    const int    nkt   = 2 * qt + 2;

    const int lm_t = lane & 7, lm_sel = lane >> 3;

    // ---- Prologue: issue cp.async for tile 0 -> stage 0.
    {
#pragma unroll
        for (int it = 0; it < 2; it++) {
            int v = tid + it * 256;
            int row = v >> 3, c = v & 7;
            cp16(smb + (row * AW + c * 4) * 4,
                 &K[base + (size_t)(row) * EMB + c * 8]);
        }
#pragma unroll
        for (int it = 0; it < 2; it++) {
            int v = tid + it * 256;
            int row = v >> 3, c = v & 7;
            cp16(smb + 2 * KV_STAGE_B + (row * AW + c * 4) * 4,
                 &V[base + (size_t)(row) * EMB + c * 8]);
        }
        CP_COMMIT();
    }

    // ---- Stage Q tile into Ps, lift to fragments.
#pragma unroll
    for (int it = 0; it < 4; it++) {
        int v = tid + it * 256;
        int row = v >> 3, c = v & 7;
        uint4 t = *(const uint4*)&Q[base + (size_t)(qbase + row) * EMB + c * 8];
        *(uint4*)&PsW[row * AW + c * 4] = t;
    }
    __syncthreads();

    uint32_t qa[4][4];
    {
        const int r0 = w * 16 + g;
#pragma unroll
        for (int kc = 0; kc < 4; kc++) {
            qa[kc][0] = PsW[(r0    ) * AW + kc * 8 + tig];
            qa[kc][1] = PsW[(r0 + 8) * AW + kc * 8 + tig];
            qa[kc][2] = PsW[(r0    ) * AW + kc * 8 + 4 + tig];
            qa[kc][3] = PsW[(r0 + 8) * AW + kc * 8 + 4 + tig];
        }
    }

    float m0 = -1e30f, m1 = -1e30f, l0 = 0.f, l1 = 0.f;
    float o[8][4];
#pragma unroll
    for (int ni = 0; ni < 8; ni++)
#pragma unroll
        for (int j = 0; j < 4; j++) o[ni][j] = 0.f;

    const float scale2 = 0.125f * 1.44269504089f;
    const int qrow_max = qbase + w * 16 + 15;

    for (int kt = 0; kt < nkt; kt++) {
        CP_WAIT0();
        __syncthreads();

        if (kt + 1 < nkt) {
            const int ns = (kt + 1) & 1;
#pragma unroll
            for (int it = 0; it < 2; it++) {
                int v = tid + it * 256;
                int row = v >> 3, c = v & 7;
                cp16(smb + ns * KV_STAGE_B + (row * AW + c * 4) * 4,
                     &K[base + (size_t)((kt + 1) * 64 + row) * EMB + c * 8]);
            }
#pragma unroll
            for (int it = 0; it < 2; it++) {
                int v = tid + it * 256;
                int row = v >> 3, c = v & 7;
                cp16(smb + 2 * KV_STAGE_B + ns * KV_STAGE_B + (row * AW + c * 4) * 4,
                     &V[base + (size_t)((kt + 1) * 64 + row) * EMB + c * 8]);
            }
            CP_COMMIT();
        }

        if (kt * 64 > qrow_max) continue;

        const uint32_t KsS = smb + (kt & 1) * KV_STAGE_B;
        const uint32_t VsS = smb + 2 * KV_STAGE_B + (kt & 1) * KV_STAGE_B;

        float sc[8][4];
#pragma unroll
        for (int ni = 0; ni < 8; ni++)
            sc[ni][0] = sc[ni][1] = sc[ni][2] = sc[ni][3] = 0.f;
#pragma unroll
        for (int np = 0; np < 4; np++) {
#pragma unroll
            for (int kc = 0; kc < 4; kc++) {
                int row  = np * 16 + ((lm_sel >> 1) << 3) + lm_t;
                int hoff = kc * 16 + ((lm_sel & 1) << 3);
                uint32_t b0, b1, b2, b3;
                ldm_x4(b0, b1, b2, b3, KsS + row * (AW * 4) + hoff * 2);
                uint32_t bfA[2] = {b0, b1}, bfB[2] = {b2, b3};
                mma_f16(sc[2 * np],     qa[kc], bfA);
                mma_f16(sc[2 * np + 1], qa[kc], bfB);
            }
        }

        const bool diag = (kt * 64 + 63 > qbase + w * 16);
        const int qg0 = qbase + w * 16 + g, qg1 = qg0 + 8;
#pragma unroll
        for (int ni = 0; ni < 8; ni++) {
#pragma unroll
            for (int j = 0; j < 4; j++) sc[ni][j] *= scale2;
            if (diag) {
                int kg = kt * 64 + ni * 8 + 2 * tig;
                if (kg     > qg0) sc[ni][0] = -1e30f;
                if (kg + 1 > qg0) sc[ni][1] = -1e30f;
                if (kg     > qg1) sc[ni][2] = -1e30f;
                if (kg + 1 > qg1) sc[ni][3] = -1e30f;
            }
        }

        float rm0 = -1e30f, rm1 = -1e30f;
#pragma unroll
        for (int ni = 0; ni < 8; ni++) {
            rm0 = fmaxf(rm0, fmaxf(sc[ni][0], sc[ni][1]));
            rm1 = fmaxf(rm1, fmaxf(sc[ni][2], sc[ni][3]));
        }
        rm0 = qmax(rm0); rm1 = qmax(rm1);
        float mn0 = fmaxf(m0, rm0), mn1 = fmaxf(m1, rm1);
        float a0 = exp2p(m0 - mn0), a1 = exp2p(m1 - mn1);
        m0 = mn0; m1 = mn1;
#pragma unroll
        for (int ni = 0; ni < 8; ni++) {
            o[ni][0] *= a0; o[ni][1] *= a0;
            o[ni][2] *= a1; o[ni][3] *= a1;
        }
        float s0 = 0.f, s1 = 0.f;
        const int pr0 = w * 16 + g;
#pragma unroll
        for (int ni = 0; ni < 8; ni++) {
            float p0 = exp2p(sc[ni][0] - mn0);
            float p1 = exp2p(sc[ni][1] - mn0);
            float p2 = exp2p(sc[ni][2] - mn1);
            float p3 = exp2p(sc[ni][3] - mn1);
            s0 += p0 + p1; s1 += p2 + p3;
            PsW[(pr0    ) * AW + ni * 4 + tig] = pack_h2(p0, p1);
            PsW[(pr0 + 8) * AW + ni * 4 + tig] = pack_h2(p2, p3);
        }
        l0 = l0 * a0 + qsum(s0);
        l1 = l1 * a1 + qsum(s1);
        __syncwarp();

#pragma unroll
        for (int kc = 0; kc < 4; kc++) {
            uint32_t pa[4];
            pa[0] = PsW[(pr0    ) * AW + kc * 8 + tig];
            pa[1] = PsW[(pr0 + 8) * AW + kc * 8 + tig];
            pa[2] = PsW[(pr0    ) * AW + kc * 8 + 4 + tig];
            pa[3] = PsW[(pr0 + 8) * AW + kc * 8 + 4 + tig];
#pragma unroll
            for (int ndp = 0; ndp < 4; ndp++) {
                int row  = kc * 16 + ((lm_sel & 1) << 3) + lm_t;
                int hoff = ndp * 16 + ((lm_sel >> 1) << 3);
                uint32_t b0, b1, b2, b3;
                ldm_x4_t(b0, b1, b2, b3, VsS + row * (AW * 4) + hoff * 2);
                uint32_t bfA[2] = {b0, b1}, bfB[2] = {b2, b3};
                mma_f16(o[2 * ndp],     pa, bfA);
                mma_f16(o[2 * ndp + 1], pa, bfB);
            }
        }
        __syncwarp();
    }

    const float inv0 = 1.f / l0, inv1 = 1.f / l1;
    const int q0 = qbase + w * 16 + g;
#pragma unroll
    for (int nd = 0; nd < 8; nd++) {
        int col = nd * 8 + 2 * tig;
        *(uint32_t*)&O[base + (size_t)q0 * EMB + col] =
            pack_h2(o[nd][0] * inv0, o[nd][1] * inv0);
        *(uint32_t*)&O[base + (size_t)(q0 + 8) * EMB + col] =
            pack_h2(o[nd][2] * inv1, o[nd][3] * inv1);
    }
}

// ---------------------------------------------------------------------------
extern "C" void kernel_launch(void* const* d_in, const int* in_sizes, int n_in,
                              void* d_out, int out_size)
{
    const float* x  = (const float*)d_in[0];
    // d_in[1] = mask (exact causal tril) -- applied analytically
    const float* Wq = (const float*)d_in[2];
    const float* Wk = (const float*)d_in[3];
    const float* Wv = (const float*)d_in[4];
    const float* Wo = (const float*)d_in[5];
    const float* bo = (const float*)d_in[6];
    float* out = (float*)d_out;

    __half *Qh, *Kh, *Vh, *Ah, *Xh, *Wqh, *Wkh, *Wvh, *Woh;
    cudaGetSymbolAddress((void**)&Qh, g_Qh);
    cudaGetSymbolAddress((void**)&Kh, g_Kh);
    cudaGetSymbolAddress((void**)&Vh, g_Vh);
    cudaGetSymbolAddress((void**)&Ah, g_Ah);
    cudaGetSymbolAddress((void**)&Xh, g_Xh);
    cudaGetSymbolAddress((void**)&Wqh, g_Wqh);
    cudaGetSymbolAddress((void**)&Wkh, g_Wkh);
    cudaGetSymbolAddress((void**)&Wvh, g_Wvh);
    cudaGetSymbolAddress((void**)&Woh, g_Woh);

    cudaFuncSetAttribute(gemm_qkv, cudaFuncAttributeMaxDynamicSharedMemorySize, GEMM_SMEM);
    cudaFuncSetAttribute(gemm_out, cudaFuncAttributeMaxDynamicSharedMemorySize, GEMM_SMEM);
    cudaFuncSetAttribute(attn_mma, cudaFuncAttributeMaxDynamicSharedMemorySize, ATTN_SMEM);

    const size_t total = (size_t)ROWS * EMB + 4 * (size_t)EMB * EMB;
    cvt_all<<<(int)(total / (256 * 8)), 256>>>(x, Wq, Wk, Wv, Wo,
                                               Xh, Wqh, Wkh, Wvh, Woh);

    dim3 qkvgrid(24, ROWS / 128);       // (24, 32)
    gemm_qkv<<<qkvgrid, 256, GEMM_SMEM>>>(Xh, Wqh, Wkh, Wvh, Qh, Kh, Vh);

    dim3 agrid(16, 2 * NHEADS);         // (16, 32)
    attn_mma<<<agrid, 256, ATTN_SMEM>>>(Qh, Kh, Vh, Ah);

    dim3 ogrid(EMB / 128, ROWS / 128);  // (8, 32)
    gemm_out<<<ogrid, 256, GEMM_SMEM>>>(Ah, Woh, bo, out);
}